// round 15
// baseline (speedup 1.0000x reference)
#include <cuda_runtime.h>
#include <cuda_bf16.h>
#include <cstdint>
#include <math.h>

#define Bb 4
#define Cc 512
#define Tt 4096
#define Ee 1024
#define Hh 16
#define Dd 64
#define Ff 256
#define CO 1536
#define EPS 1e-6f

typedef __nv_bfloat16 bf;

// ---------------- scratch ----------------
__device__ __align__(1024) bf g_xh[Bb*Tt*Cc],  g_xl[Bb*Tt*Cc];
__device__ __align__(1024) bf g_Qh[Bb*Tt*Ee],  g_Ql[Bb*Tt*Ee];
__device__ __align__(1024) bf g_Kh[Bb*Tt*Ee],  g_Kl[Bb*Tt*Ee];
__device__ __align__(1024) bf g_Vth[Bb*Ee*Tt], g_Vtl[Bb*Ee*Tt];
__device__ __align__(1024) bf g_Wqh[Ee*Cc],    g_Wql[Ee*Cc];
__device__ __align__(1024) bf g_Wkh[Ee*Cc],    g_Wkl[Ee*Cc];
__device__ __align__(1024) bf g_Wvh[Ee*Cc],    g_Wvl[Ee*Cc];
__device__ __align__(1024) bf g_Woh[Ee*Ee],    g_Wol[Ee*Ee];
__device__ __align__(1024) bf g_ph[Ff*Dd],     g_pl[Ff*Dd];
__device__ __align__(1024) bf g_Kpth[Bb*Hh*Ff*Tt], g_Kptl[Bb*Hh*Ff*Tt];
__device__ __align__(1024) bf g_ah[Bb*Tt*Ee],  g_al[Bb*Tt*Ee];
__device__ __align__(1024) bf g_KVth[Bb*Hh*64*Ff], g_KVtl[Bb*Hh*64*Ff];
__device__ float g_KVt[Bb*Hh*64*Ff];
__device__ float g_Ksum[Bb*Hh*Ff];
__device__ unsigned g_c0, g_c1;

// ================= PTX helpers =================
__device__ __forceinline__ uint32_t s2u(const void* p){
    uint32_t a;
    asm("{ .reg .u64 t; cvta.to.shared.u64 t, %1; cvt.u32.u64 %0, t; }" : "=r"(a) : "l"(p));
    return a;
}
__device__ __forceinline__ uint32_t swz(uint32_t off){ return off ^ ((off >> 3) & 0x70); }

__device__ __forceinline__ void ldsm4(uint32_t& r0, uint32_t& r1, uint32_t& r2, uint32_t& r3, uint32_t addr){
    asm volatile("ldmatrix.sync.aligned.m8n8.x4.shared.b16 {%0,%1,%2,%3}, [%4];"
        : "=r"(r0), "=r"(r1), "=r"(r2), "=r"(r3) : "r"(addr));
}
__device__ __forceinline__ void mma_bf16(float* c, const uint32_t* a, const uint32_t* b){
    asm volatile("mma.sync.aligned.m16n8k16.row.col.f32.bf16.bf16.f32 "
        "{%0,%1,%2,%3}, {%4,%5,%6,%7}, {%8,%9}, {%0,%1,%2,%3};"
        : "+f"(c[0]), "+f"(c[1]), "+f"(c[2]), "+f"(c[3])
        : "r"(a[0]), "r"(a[1]), "r"(a[2]), "r"(a[3]), "r"(b[0]), "r"(b[1]));
}
__device__ __forceinline__ void cpa16(uint32_t s, const void* g){
    asm volatile("cp.async.cg.shared.global [%0], [%1], 16;" :: "r"(s), "l"(g));
}
__device__ __forceinline__ void cpa_commit(){ asm volatile("cp.async.commit_group;" ::: "memory"); }
__device__ __forceinline__ void cpa_wait0(){ asm volatile("cp.async.wait_group 0;" ::: "memory"); }
__device__ __forceinline__ void cpa_wait1(){ asm volatile("cp.async.wait_group 1;" ::: "memory"); }
__device__ __forceinline__ void cpa_wait2(){ asm volatile("cp.async.wait_group 2;" ::: "memory"); }

__device__ __forceinline__ void split2(float a, bf& h, bf& l){
    h = __float2bfloat16(a);
    l = __float2bfloat16(a - __bfloat162float(h));
}

// ================= small kernels =================
__global__ void k_prep_proj(const float* __restrict__ proj){
    int i = blockIdx.x * 256 + threadIdx.x;
    if (i == 0){ g_c0 = 0; g_c1 = 0; }
    if (i < Ff*Dd){ bf hi, lo; split2(proj[i], hi, lo); g_ph[i] = hi; g_pl[i] = lo; }
    if (i < Bb*Hh*64*Ff) g_KVt[i] = 0.f;
    if (i < Bb*Hh*Ff)    g_Ksum[i] = 0.f;
}
__global__ void k_prep_x(const float* __restrict__ x, float* __restrict__ out){
    __shared__ float tile[32][33];
    int b = blockIdx.z, t0 = blockIdx.x*32, c0 = blockIdx.y*32;
    int tx = threadIdx.x, ty = threadIdx.y;
    for (int i = ty; i < 32; i += 8){
        float v = x[((size_t)b*Cc + c0 + i)*Tt + t0 + tx];
        tile[i][tx] = v;
        out[((size_t)b*CO + c0 + i)*Tt + t0 + tx] = v;
    }
    __syncthreads();
    for (int i = ty; i < 32; i += 8){
        bf hi, lo; split2(tile[tx][i], hi, lo);
        size_t o = ((size_t)b*Tt + t0 + i)*Cc + c0 + tx;
        g_xh[o] = hi; g_xl[o] = lo;
    }
}
__global__ void k_prep_w(const float* __restrict__ Wq, const float* __restrict__ Wk,
                         const float* __restrict__ Wv, const float* __restrict__ Wo){
    const int Nd = Ee;
    int z = blockIdx.z;
    int Kd = (z == 3) ? Ee : Cc;
    int k0 = blockIdx.y*32;
    if (k0 >= Kd) return;
    const float* W = z == 0 ? Wq : z == 1 ? Wk : z == 2 ? Wv : Wo;
    bf* Dh = z == 0 ? g_Wqh : z == 1 ? g_Wkh : z == 2 ? g_Wvh : g_Woh;
    bf* Dl = z == 0 ? g_Wql : z == 1 ? g_Wkl : z == 2 ? g_Wvl : g_Wol;
    __shared__ float tile[32][33];
    int n0 = blockIdx.x*32;
    int tx = threadIdx.x, ty = threadIdx.y;
    for (int i = ty; i < 32; i += 8)
        tile[i][tx] = W[(size_t)(k0 + i)*Nd + n0 + tx];
    __syncthreads();
    for (int i = ty; i < 32; i += 8){
        bf hi, lo; split2(tile[tx][i], hi, lo);
        size_t o = (size_t)(n0 + i)*Kd + k0 + tx;
        Dh[o] = hi; Dl[o] = lo;
    }
}
__global__ void k_cvt_kv(){
    int i = blockIdx.x * 256 + threadIdx.x;
    if (i < Bb*Hh*64*Ff){ bf h, l; split2(g_KVt[i], h, l); g_KVth[i] = h; g_KVtl[i] = l; }
}

// ================= tile loaders =================
template<int NROWS>   // 256-thread version
__device__ __forceinline__ void load_tileN(uint32_t sbase, const bf* g, int row0, int stride, int k0, int tid){
#pragma unroll
    for (int i = 0; i < NROWS/32; i++){
        int idx = tid + i*256;
        int r = idx >> 3, kc = idx & 7;
        cpa16(sbase + swz((uint32_t)(r*128 + kc*16)), g + (size_t)(row0 + r)*stride + k0 + kc*8);
    }
}
// 512-thread version, 128 rows
__device__ __forceinline__ void load_tile512(uint32_t sbase, const bf* g, int row0, int stride, int k0, int tid){
#pragma unroll
    for (int i = 0; i < 2; i++){
        int idx = tid + i*512;
        int r = idx >> 3, kc = idx & 7;
        cpa16(sbase + swz((uint32_t)(r*128 + kc*16)), g + (size_t)(row0 + r)*stride + k0 + kc*8);
    }
}

#define STAGE_BYTES 65536

// ================= persistent GEMM: 128x128 tile, 512 threads, 32x32 warp tiles =================
#define PERS_DSM (3*STAGE_BYTES + 16512)

template<int MODE>
__global__ __launch_bounds__(512, 1) void k_mmaP(float* __restrict__ outp){
    constexpr int NKT   = (MODE == 0) ? 8 : 16;
    constexpr int KA    = (MODE == 0) ? Cc : Ee;
    constexpr int TOTAL = (MODE == 0) ? 3072 : 1024;

    extern __shared__ __align__(1024) char dsm[];
    float* fb = (float*)(dsm + 3*STAGE_BYTES);   // 32 x 129 fp32
    __shared__ int s_cur, s_next;
    uint32_t sb = s2u(dsm);
    int tid = threadIdx.x, lane = tid & 31, w = tid >> 5;   // 16 warps
    unsigned* ctr = (MODE == 0) ? &g_c0 : &g_c1;

    if (tid == 0){ s_cur = (int)atomicAdd(ctr, 1u); s_next = (int)atomicAdd(ctr, 1u); }
    __syncthreads();
    int cur = s_cur, nxt = s_next;
    if (cur >= TOTAL) return;

    const bf* Ahp = (MODE == 0) ? g_xh : g_ah;
    const bf* Alp = (MODE == 0) ? g_xl : g_al;

    auto decode = [&](int id, int& rowA, int& rowB, const bf*& Bh2, const bf*& Bl2, int& z){
        if (MODE == 0){
            z = id >> 10; int r = id & 1023;
            rowB = (r >> 7) * 128; rowA = (r & 127) * 128;
            Bh2 = z == 0 ? g_Wqh : z == 1 ? g_Wkh : g_Wvh;
            Bl2 = z == 0 ? g_Wql : z == 1 ? g_Wkl : g_Wvl;
        } else {
            z = 0;
            rowB = (id >> 7) * 128; rowA = (id & 127) * 128;
            Bh2 = g_Woh; Bl2 = g_Wol;
        }
    };
    auto commitStage = [&](int slot, int rA, int rB, const bf* bh, const bf* bl, int k0){
        uint32_t st_ = sb + (uint32_t)slot * STAGE_BYTES;
        load_tile512(st_,         Ahp, rA, KA, k0, tid);
        load_tile512(st_ + 16384, Alp, rA, KA, k0, tid);
        load_tile512(st_ + 32768, bh,  rB, KA, k0, tid);
        load_tile512(st_ + 49152, bl,  rB, KA, k0, tid);
        cpa_commit();
    };

    int rowA, rowB, zc; const bf *Bh2, *Bl2;
    decode(cur, rowA, rowB, Bh2, Bl2, zc);
    commitStage(0, rowA, rowB, Bh2, Bl2, 0);
    commitStage(1, rowA, rowB, Bh2, Bl2, 64);
    int committed = 2, s = 0;

    int rr = lane & 7, sub = lane >> 3;
    int wm = (w & 3) * 32, wn = (w >> 2) * 32;
    int arow = wm + rr + (sub & 1) * 8;
    int acb0 = (sub >> 1) * 16;
    int brow = wn + rr + (sub >> 1) * 8;
    int bcb0 = (sub & 1) * 16;
    int r0row = lane >> 2, c0 = (lane & 3) * 2;

    while (true){
        float acc[2][4][4];
#pragma unroll
        for (int i = 0; i < 2; i++)
#pragma unroll
            for (int j = 0; j < 4; j++)
#pragma unroll
                for (int c = 0; c < 4; c++) acc[i][j][c] = 0.f;

        for (int kt = 0; kt < NKT; kt++){
            int allowed = committed - s - 1;
            if (allowed >= 2) cpa_wait2(); else if (allowed == 1) cpa_wait1(); else cpa_wait0();
            __syncthreads();

            int kt2 = kt + 2;
            if (kt2 < NKT){
                commitStage((s + 2) % 3, rowA, rowB, Bh2, Bl2, kt2*64); committed++;
            } else if (nxt < TOTAL){
                int rA2, rB2, z2; const bf *bh2, *bl2;
                decode(nxt, rA2, rB2, bh2, bl2, z2);
                commitStage((s + 2) % 3, rA2, rB2, bh2, bl2, (kt2 - NKT)*64); committed++;
            }

            uint32_t st = sb + (uint32_t)(s % 3) * STAGE_BYTES;
#pragma unroll
            for (int ks = 0; ks < 4; ks++){
                uint32_t ahf[2][4], alf[2][4], bhf[4][2], blf[4][2];
#pragma unroll
                for (int i = 0; i < 2; i++){
                    uint32_t sa = swz((uint32_t)((arow + i*16)*128 + acb0 + ks*32));
                    ldsm4(ahf[i][0], ahf[i][1], ahf[i][2], ahf[i][3], st + sa);
                    ldsm4(alf[i][0], alf[i][1], alf[i][2], alf[i][3], st + 16384 + sa);
                }
#pragma unroll
                for (int j2 = 0; j2 < 2; j2++){
                    uint32_t sa = swz((uint32_t)((brow + j2*16)*128 + bcb0 + ks*32));
                    uint32_t r0, r1, r2, r3;
                    ldsm4(r0, r1, r2, r3, st + 32768 + sa);
                    bhf[j2*2][0] = r0; bhf[j2*2][1] = r1; bhf[j2*2+1][0] = r2; bhf[j2*2+1][1] = r3;
                    ldsm4(r0, r1, r2, r3, st + 49152 + sa);
                    blf[j2*2][0] = r0; blf[j2*2][1] = r1; blf[j2*2+1][0] = r2; blf[j2*2+1][1] = r3;
                }
#pragma unroll
                for (int i = 0; i < 2; i++)
#pragma unroll
                    for (int j = 0; j < 4; j++){
                        mma_bf16(acc[i][j], ahf[i], bhf[j]);
                        mma_bf16(acc[i][j], ahf[i], blf[j]);
                        mma_bf16(acc[i][j], alf[i], bhf[j]);
                    }
            }
            s++;
        }

        int m0 = rowA, n0 = rowB;
        if (MODE == 0 && zc < 2){
            bf* Dh = zc ? g_Kh : g_Qh;
            bf* Dl = zc ? g_Kl : g_Ql;
#pragma unroll
            for (int i = 0; i < 2; i++)
#pragma unroll
                for (int j = 0; j < 4; j++)
#pragma unroll
                    for (int half = 0; half < 2; half++){
                        int row = m0 + wm + i*16 + r0row + half*8;
                        int col = n0 + wn + j*8 + c0;
                        bf h0, l0, h1, l1;
                        split2(acc[i][j][half*2], h0, l0);
                        split2(acc[i][j][half*2 + 1], h1, l1);
                        *(__nv_bfloat162*)&Dh[(size_t)row*Ee + col] = __nv_bfloat162{h0, h1};
                        *(__nv_bfloat162*)&Dl[(size_t)row*Ee + col] = __nv_bfloat162{l0, l1};
                    }
        } else {
            // transpose via 4 passes of 32 rows through fb; warps with (w&3)==p own pass p
            int b = m0 / Tt, t0 = m0 % Tt;
            __syncthreads();
#pragma unroll
            for (int p = 0; p < 4; p++){
                if ((w & 3) == p){
#pragma unroll
                    for (int i = 0; i < 2; i++)
#pragma unroll
                        for (int j = 0; j < 4; j++)
#pragma unroll
                            for (int half = 0; half < 2; half++){
                                int row = i*16 + r0row + half*8;   // local 0..31
                                int col = wn + j*8 + c0;
                                fb[row*129 + col]     = acc[i][j][half*2];
                                fb[row*129 + col + 1] = acc[i][j][half*2 + 1];
                            }
                }
                __syncthreads();
                if (MODE == 0){
                    for (int idx = tid; idx < 4096; idx += 512){
                        int n = idx >> 5, t = idx & 31;
                        bf h, l; split2(fb[t*129 + n], h, l);
                        size_t o = (size_t)(b*Ee + n0 + n)*Tt + t0 + p*32 + t;
                        g_Vth[o] = h; g_Vtl[o] = l;
                    }
                } else {
                    for (int idx = tid; idx < 4096; idx += 512){
                        int n = idx >> 5, t = idx & 31;
                        outp[(size_t)b*CO*Tt + (size_t)(Cc + n0 + n)*Tt + t0 + p*32 + t] = fb[t*129 + n];
                    }
                }
                __syncthreads();
            }
        }

        if (nxt >= TOTAL) break;
        cur = nxt;
        decode(cur, rowA, rowB, Bh2, Bl2, zc);
        if (tid == 0) s_next = (int)atomicAdd(ctr, 1u);
        __syncthreads();
        nxt = s_next;
    }
}

// ================= k_featK: Kp = exp(K@proj^T)+eps -> transposed split gmem + Ksum =================
#define FEATK_DSM (32768 + 65536 + 66048)

__global__ __launch_bounds__(256, 1) void k_featK(){
    extern __shared__ __align__(1024) char dsm[];
    uint32_t sb = s2u(dsm);
    int tid = threadIdx.x, lane = tid & 31, w = tid >> 5;
    int bh = blockIdx.z;
    int m0 = blockIdx.x * 512, n0 = blockIdx.y * 128;
    const bf* Ah = g_Kh + (bh & 15)*Dd;
    const bf* Al = g_Kl + (bh & 15)*Dd;
    int rowBase = (bh >> 4)*Tt + m0;

    load_tileN<128>(sb,         g_ph, n0, Dd, 0, tid);
    load_tileN<128>(sb + 16384, g_pl, n0, Dd, 0, tid);
    load_tileN<128>(sb + 32768,         Ah, rowBase, Ee, 0, tid);
    load_tileN<128>(sb + 32768 + 16384, Al, rowBase, Ee, 0, tid);
    cpa_commit();
    load_tileN<128>(sb + 65536,         Ah, rowBase + 128, Ee, 0, tid);
    load_tileN<128>(sb + 65536 + 16384, Al, rowBase + 128, Ee, 0, tid);
    cpa_commit();

    int rr = lane & 7, sub = lane >> 3;
    int wm = (w & 1) * 64, wn = (w >> 1) * 32;
    int arow = wm + rr + (sub & 1) * 8;
    int acb0 = (sub >> 1) * 16;
    int brow = wn + rr + (sub >> 1) * 8;
    int bcb0 = (sub & 1) * 16;
    float* fb = (float*)(dsm + 32768 + 65536);

    for (int it = 0; it < 4; it++){
        uint32_t stA = sb + 32768 + (uint32_t)(it & 1) * 32768;
        if (it < 3) cpa_wait1(); else cpa_wait0();
        __syncthreads();

        float acc[4][4][4];
#pragma unroll
        for (int i = 0; i < 4; i++)
#pragma unroll
            for (int j = 0; j < 4; j++)
#pragma unroll
                for (int c = 0; c < 4; c++) acc[i][j][c] = 0.f;

#pragma unroll
        for (int ks = 0; ks < 4; ks++){
            uint32_t ahf[4][4], alf[4][4], bhf[4][2], blf[4][2];
#pragma unroll
            for (int i = 0; i < 4; i++){
                uint32_t sa = swz((uint32_t)((arow + i*16)*128 + acb0 + ks*32));
                ldsm4(ahf[i][0], ahf[i][1], ahf[i][2], ahf[i][3], stA + sa);
                ldsm4(alf[i][0], alf[i][1], alf[i][2], alf[i][3], stA + 16384 + sa);
            }
#pragma unroll
            for (int j2 = 0; j2 < 2; j2++){
                uint32_t sa = swz((uint32_t)((brow + j2*16)*128 + bcb0 + ks*32));
                uint32_t r0, r1, r2, r3;
                ldsm4(r0, r1, r2, r3, sb + sa);
                bhf[j2*2][0] = r0; bhf[j2*2][1] = r1; bhf[j2*2+1][0] = r2; bhf[j2*2+1][1] = r3;
                ldsm4(r0, r1, r2, r3, sb + 16384 + sa);
                blf[j2*2][0] = r0; blf[j2*2][1] = r1; blf[j2*2+1][0] = r2; blf[j2*2+1][1] = r3;
            }
#pragma unroll
            for (int i = 0; i < 4; i++)
#pragma unroll
                for (int j = 0; j < 4; j++){
                    mma_bf16(acc[i][j], ahf[i], bhf[j]);
                    mma_bf16(acc[i][j], ahf[i], blf[j]);
                    mma_bf16(acc[i][j], alf[i], bhf[j]);
                }
        }
        __syncthreads();
        if (it + 2 < 4){
            load_tileN<128>(stA,         Ah, rowBase + (it + 2)*128, Ee, 0, tid);
            load_tileN<128>(stA + 16384, Al, rowBase + (it + 2)*128, Ee, 0, tid);
            cpa_commit();
        }

        int r0row = lane >> 2, c0 = (lane & 3) * 2;
        int mt = it * 128;
#pragma unroll
        for (int i = 0; i < 4; i++)
#pragma unroll
            for (int j = 0; j < 4; j++)
#pragma unroll
                for (int half = 0; half < 2; half++){
                    int row = wm + i*16 + r0row + half*8;
                    int col = wn + j*8 + c0;
                    fb[row*129 + col]     = expf(acc[i][j][half*2]) + EPS;
                    fb[row*129 + col + 1] = expf(acc[i][j][half*2 + 1]) + EPS;
                }
        __syncthreads();
        for (int idx = tid; idx < 16384; idx += 256){
            int f = idx >> 7, t = idx & 127;
            bf h, l; split2(fb[t*129 + f], h, l);
            size_t o = (size_t)(bh*Ff + n0 + f)*Tt + m0 + mt + t;
            g_Kpth[o] = h; g_Kptl[o] = l;
        }
        {
            int f = tid >> 1, th = tid & 1;
            float s = 0.f;
#pragma unroll 8
            for (int t = th*64; t < th*64 + 64; t++) s += fb[t*129 + f];
            atomicAdd(&g_Ksum[bh*Ff + n0 + f], s);
        }
        __syncthreads();
    }
}

// ================= k_kv: KV += Kp^T @ V^T over 512-T chunks =================
#define MMA_DSM 196608

__global__ __launch_bounds__(256, 1) void k_kv(){
    constexpr int NKT = 8;
    extern __shared__ __align__(1024) char dsm[];
    uint32_t sb = s2u(dsm);
    int tid = threadIdx.x, lane = tid & 31, w = tid >> 5;
    int bz = blockIdx.z;
    int m0 = blockIdx.x * 128;

    const bf* Ahp = g_Kpth;
    const bf* Alp = g_Kptl;
    int rowA0 = bz*Ff + m0;
    int rowB0 = (bz >> 4)*Ee + (bz & 15)*Dd;
    int k0base = blockIdx.y * 512;

    float acc[4][2][4];
#pragma unroll
    for (int i = 0; i < 4; i++)
#pragma unroll
        for (int j = 0; j < 2; j++)
#pragma unroll
            for (int c = 0; c < 4; c++) acc[i][j][c] = 0.f;

#define LOADSTG(s, k0) do { \
        uint32_t st_ = sb + (uint32_t)(s)*STAGE_BYTES; \
        load_tileN<128>(st_,         Ahp, rowA0, Tt, (k0), tid); \
        load_tileN<128>(st_ + 16384, Alp, rowA0, Tt, (k0), tid); \
        load_tileN<64>(st_ + 32768,  g_Vth, rowB0, Tt, (k0), tid); \
        load_tileN<64>(st_ + 40960,  g_Vtl, rowB0, Tt, (k0), tid); \
        cpa_commit(); \
    } while(0)

    LOADSTG(0, k0base);
    LOADSTG(1, k0base + 64);
    int committed = 2;

    int rr = lane & 7, sub = lane >> 3;
    int wm = (w & 1) * 64, wn = (w >> 1) * 16;
    int arow = wm + rr + (sub & 1) * 8;
    int acb0 = (sub >> 1) * 16;
    int brow = wn + rr + (sub >> 1) * 8;
    int bcb0 = (sub & 1) * 16;

    for (int kt = 0; kt < NKT; kt++){
        int allowed = committed - kt - 1;
        if (allowed >= 2) cpa_wait2(); else if (allowed == 1) cpa_wait1(); else cpa_wait0();
        __syncthreads();
        if (kt + 2 < NKT){ LOADSTG((kt + 2) % 3, k0base + (kt + 2)*64); committed++; }

        uint32_t st = sb + (uint32_t)(kt % 3) * STAGE_BYTES;
#pragma unroll
        for (int ks = 0; ks < 4; ks++){
            uint32_t ahf[4][4], alf[4][4], bhf[2][2], blf[2][2];
#pragma unroll
            for (int i = 0; i < 4; i++){
                uint32_t sa = swz((uint32_t)((arow + i*16)*128 + acb0 + ks*32));
                ldsm4(ahf[i][0], ahf[i][1], ahf[i][2], ahf[i][3], st + sa);
                ldsm4(alf[i][0], alf[i][1], alf[i][2], alf[i][3], st + 16384 + sa);
            }
            {
                uint32_t sa = swz((uint32_t)(brow*128 + bcb0 + ks*32));
                uint32_t r0, r1, r2, r3;
                ldsm4(r0, r1, r2, r3, st + 32768 + sa);
                bhf[0][0] = r0; bhf[0][1] = r1; bhf[1][0] = r2; bhf[1][1] = r3;
                ldsm4(r0, r1, r2, r3, st + 40960 + sa);
                blf[0][0] = r0; blf[0][1] = r1; blf[1][0] = r2; blf[1][1] = r3;
            }
#pragma unroll
            for (int i = 0; i < 4; i++)
#pragma unroll
                for (int j = 0; j < 2; j++){
                    mma_bf16(acc[i][j], ahf[i], bhf[j]);
                    mma_bf16(acc[i][j], ahf[i], blf[j]);
                    mma_bf16(acc[i][j], alf[i], bhf[j]);
                }
        }
    }
#undef LOADSTG

    int r0row = lane >> 2, c0 = (lane & 3) * 2;
    float* fb = (float*)dsm;
    __syncthreads();
#pragma unroll
    for (int i = 0; i < 4; i++)
#pragma unroll
        for (int j = 0; j < 2; j++)
#pragma unroll
            for (int half = 0; half < 2; half++){
                int row = wm + i*16 + r0row + half*8;
                int col = wn + j*8 + c0;
                fb[row*129 + col]     = acc[i][j][half*2];
                fb[row*129 + col + 1] = acc[i][j][half*2 + 1];
            }
    __syncthreads();
    for (int idx = tid; idx < 8192; idx += 256){
        int n = idx >> 7, f = idx & 127;
        atomicAdd(&g_KVt[((size_t)bz*64 + n)*Ff + m0 + f], fb[f*129 + n]);
    }
}

// ================= k_fattn: fused Qp + attn (R14 winner) =================
#define FA_KVH   0
#define FA_KVL   32768
#define FA_QH    65536
#define FA_QL    81920
#define FA_PJH   98304
#define FA_PJL   131072
#define FA_QPH   163840
#define FA_QPL   196608
#define FA_DEN   229376
#define FA_KS    229888
#define FATTN_DSM 230912

__global__ __launch_bounds__(256, 1) void k_fattn(){
    extern __shared__ __align__(1024) char dsm[];
    uint32_t sb = s2u(dsm);
    float* sden = (float*)(dsm + FA_DEN);
    float* sKs  = (float*)(dsm + FA_KS);
    int tid = threadIdx.x, lane = tid & 31, w = tid >> 5;
    int bh = blockIdx.z;
    int t0 = blockIdx.x * 128;
    int b = bh >> 4, h = bh & 15;
    int qrow0 = b*Tt + t0;
    int kvrow0 = bh*64;

    if (tid < 128) sden[tid] = 0.f;
    sKs[tid] = g_Ksum[bh*Ff + tid];

#pragma unroll
    for (int i = 0; i < 8; i++){
        int idx = tid + i*256;
        int ch = idx >> 9, r = (idx >> 3) & 63, kc = idx & 7;
        uint32_t sa = (uint32_t)(ch*8192) + swz((uint32_t)(r*128 + kc*16));
        cpa16(sb + FA_KVH + sa, g_KVth + (size_t)(kvrow0 + r)*Ff + ch*64 + kc*8);
        cpa16(sb + FA_KVL + sa, g_KVtl + (size_t)(kvrow0 + r)*Ff + ch*64 + kc*8);
    }
    load_tileN<128>(sb + FA_QH, g_Qh + h*Dd, qrow0, Ee, 0, tid);
    load_tileN<128>(sb + FA_QL, g_Ql + h*Dd, qrow0, Ee, 0, tid);
    load_tileN<256>(sb + FA_PJH, g_ph, 0, Dd, 0, tid);
    load_tileN<256>(sb + FA_PJL, g_pl, 0, Dd, 0, tid);
    cpa_commit();
    cpa_wait0();
    __syncthreads();

    int rr = lane & 7, sub = lane >> 3;
    int wm = (w & 1) * 64;
    int wn = (w >> 1) * 32;
    int wn2 = (w >> 1) * 16;
    int arow = wm + rr + (sub & 1) * 8;
    int acb0 = (sub >> 1) * 16;
    int brow = wn + rr + (sub >> 1) * 8;
    int bcb0 = (sub & 1) * 16;
    int brow2 = wn2 + rr + (sub >> 1) * 8;
    int r0row = lane >> 2, c0 = (lane & 3) * 2;

    float acc2[4][2][4];
#pragma unroll
    for (int i = 0; i < 4; i++)
#pragma unroll
        for (int j = 0; j < 2; j++)
#pragma unroll
            for (int c = 0; c < 4; c++) acc2[i][j][c] = 0.f;

    for (int fh = 0; fh < 2; fh++){
        float acc[4][4][4];
#pragma unroll
        for (int i = 0; i < 4; i++)
#pragma unroll
            for (int j = 0; j < 4; j++)
#pragma unroll
                for (int c = 0; c < 4; c++) acc[i][j][c] = 0.f;
#pragma unroll
        for (int ks = 0; ks < 4; ks++){
            uint32_t ahf[4][4], alf[4][4], bhf[4][2], blf[4][2];
#pragma unroll
            for (int i = 0; i < 4; i++){
                uint32_t sa = swz((uint32_t)((arow + i*16)*128 + acb0 + ks*32));
                ldsm4(ahf[i][0], ahf[i][1], ahf[i][2], ahf[i][3], sb + FA_QH + sa);
                ldsm4(alf[i][0], alf[i][1], alf[i][2], alf[i][3], sb + FA_QL + sa);
            }
#pragma unroll
            for (int j2 = 0; j2 < 2; j2++){
                uint32_t sa = (uint32_t)(fh*16384) + swz((uint32_t)((brow + j2*16)*128 + bcb0 + ks*32));
                uint32_t r0, r1, r2, r3;
                ldsm4(r0, r1, r2, r3, sb + FA_PJH + sa);
                bhf[j2*2][0] = r0; bhf[j2*2][1] = r1; bhf[j2*2+1][0] = r2; bhf[j2*2+1][1] = r3;
                ldsm4(r0, r1, r2, r3, sb + FA_PJL + sa);
                blf[j2*2][0] = r0; blf[j2*2][1] = r1; blf[j2*2+1][0] = r2; blf[j2*2+1][1] = r3;
            }
#pragma unroll
            for (int i = 0; i < 4; i++)
#pragma unroll
                for (int j = 0; j < 4; j++){
                    mma_bf16(acc[i][j], ahf[i], bhf[j]);
                    mma_bf16(acc[i][j], ahf[i], blf[j]);
                    mma_bf16(acc[i][j], alf[i], bhf[j]);
                }
        }

        float dloc[8];
#pragma unroll
        for (int e = 0; e < 8; e++) dloc[e] = 0.f;
#pragma unroll
        for (int i = 0; i < 4; i++)
#pragma unroll
            for (int j = 0; j < 4; j++)
#pragma unroll
                for (int half = 0; half < 2; half++){
                    int trow = wm + i*16 + r0row + half*8;
                    int f0 = wn + j*8 + c0;
                    float v0 = expf(acc[i][j][half*2]) + EPS;
                    float v1 = expf(acc[i][j][half*2 + 1]) + EPS;
                    dloc[i*2 + half] += v0 * sKs[fh*128 + f0] + v1 * sKs[fh*128 + f0 + 1];
                    bf h0, l0, h1, l1;
                    split2(v0, h0, l0); split2(v1, h1, l1);
                    uint32_t addr = (uint32_t)((f0 >> 6)*16384) + swz((uint32_t)(trow*128 + (f0 & 63)*2));
                    *(__nv_bfloat162*)(dsm + FA_QPH + addr) = __nv_bfloat162{h0, h1};
                    *(__nv_bfloat162*)(dsm + FA_QPL + addr) = __nv_bfloat162{l0, l1};
                }
#pragma unroll
        for (int e = 0; e < 8; e++){
            float v = dloc[e];
            v += __shfl_xor_sync(0xffffffffu, v, 1);
            v += __shfl_xor_sync(0xffffffffu, v, 2);
            if ((lane & 3) == 0)
                atomicAdd(&sden[wm + (e >> 1)*16 + r0row + (e & 1)*8], v);
        }
        __syncthreads();

#pragma unroll
        for (int kc = 0; kc < 2; kc++){
            uint32_t qa = FA_QPH + (uint32_t)kc*16384;
            uint32_t ql = FA_QPL + (uint32_t)kc*16384;
            uint32_t va = FA_KVH + (uint32_t)(fh*2 + kc)*8192;
            uint32_t vl = FA_KVL + (uint32_t)(fh*2 + kc)*8192;
#pragma unroll
            for (int ks = 0; ks < 4; ks++){
                uint32_t ahf[4][4], alf[4][4], bhf[2][2], blf[2][2];
#pragma unroll
                for (int i = 0; i < 4; i++){
                    uint32_t sa = swz((uint32_t)((arow + i*16)*128 + acb0 + ks*32));
                    ldsm4(ahf[i][0], ahf[i][1], ahf[i][2], ahf[i][3], sb + qa + sa);
                    ldsm4(alf[i][0], alf[i][1], alf[i][2], alf[i][3], sb + ql + sa);
                }
                {
                    uint32_t sa = swz((uint32_t)(brow2*128 + bcb0 + ks*32));
                    uint32_t r0, r1, r2, r3;
                    ldsm4(r0, r1, r2, r3, sb + va + sa);
                    bhf[0][0] = r0; bhf[0][1] = r1; bhf[1][0] = r2; bhf[1][1] = r3;
                    ldsm4(r0, r1, r2, r3, sb + vl + sa);
                    blf[0][0] = r0; blf[0][1] = r1; blf[1][0] = r2; blf[1][1] = r3;
                }
#pragma unroll
                for (int i = 0; i < 4; i++)
#pragma unroll
                    for (int j = 0; j < 2; j++){
                        mma_bf16(acc2[i][j], ahf[i], bhf[j]);
                        mma_bf16(acc2[i][j], ahf[i], blf[j]);
                        mma_bf16(acc2[i][j], alf[i], bhf[j]);
                    }
            }
        }
        if (fh == 0) __syncthreads();
    }

    __syncthreads();
#pragma unroll
    for (int i = 0; i < 4; i++)
#pragma unroll
        for (int half = 0; half < 2; half++){
            int row = wm + i*16 + r0row + half*8;
            float inv = 1.0f / fmaxf(sden[row], 1e-6f);
#pragma unroll
            for (int j = 0; j < 2; j++){
                int col = wn2 + j*8 + c0;
                bf h0, l0, h1, l1;
                split2(acc2[i][j][half*2] * inv, h0, l0);
                split2(acc2[i][j][half*2 + 1] * inv, h1, l1);
                size_t o = (size_t)(b*Tt + t0 + row)*Ee + h*Dd + col;
                *(__nv_bfloat162*)&g_ah[o] = __nv_bfloat162{h0, h1};
                *(__nv_bfloat162*)&g_al[o] = __nv_bfloat162{l0, l1};
            }
        }
}

// ================= launch =================
extern "C" void kernel_launch(void* const* d_in, const int* in_sizes, int n_in,
                              void* d_out, int out_size) {
    const float* x    = (const float*)d_in[0];
    const float* Wq   = (const float*)d_in[1];
    const float* Wk   = (const float*)d_in[2];
    const float* Wv   = (const float*)d_in[3];
    const float* Wo   = (const float*)d_in[4];
    const float* proj = (const float*)d_in[5];
    float* out = (float*)d_out;

    cudaFuncSetAttribute(k_mmaP<0>, cudaFuncAttributeMaxDynamicSharedMemorySize, PERS_DSM);
    cudaFuncSetAttribute(k_mmaP<1>, cudaFuncAttributeMaxDynamicSharedMemorySize, PERS_DSM);
    cudaFuncSetAttribute(k_featK,   cudaFuncAttributeMaxDynamicSharedMemorySize, FEATK_DSM);
    cudaFuncSetAttribute(k_kv,      cudaFuncAttributeMaxDynamicSharedMemorySize, MMA_DSM);
    cudaFuncSetAttribute(k_fattn,   cudaFuncAttributeMaxDynamicSharedMemorySize, FATTN_DSM);

    k_prep_proj<<<(Bb*Hh*64*Ff + 255)/256, 256>>>(proj);
    k_prep_x<<<dim3(Tt/32, Cc/32, Bb), dim3(32, 8)>>>(x, out);
    k_prep_w<<<dim3(Ee/32, Ee/32, 4), dim3(32, 8)>>>(Wq, Wk, Wv, Wo);

    k_mmaP<0><<<148, 512, PERS_DSM>>>(nullptr);                            // QKV (512 threads)
    k_featK<<<dim3(Tt/512, Ff/128, Bb*Hh), 256, FEATK_DSM>>>();            // Kp + Ksum
    k_kv<<<dim3(Ff/128, 8, Bb*Hh), 256, MMA_DSM>>>();                      // KV
    k_cvt_kv<<<(Bb*Hh*64*Ff + 255)/256, 256>>>();
    k_fattn<<<dim3(Tt/128, 1, Bb*Hh), 256, FATTN_DSM>>>();                 // Qp + attn (fused)
    k_mmaP<1><<<148, 512, PERS_DSM>>>(out);                                // Wo + concat (512 threads)
}

// round 16
// speedup vs baseline: 1.0380x; 1.0380x over previous
#include <cuda_runtime.h>
#include <cuda_bf16.h>
#include <cstdint>
#include <math.h>

#define Bb 4
#define Cc 512
#define Tt 4096
#define Ee 1024
#define Hh 16
#define Dd 64
#define Ff 256
#define CO 1536
#define EPS 1e-6f

typedef __nv_bfloat16 bf;

// ---------------- scratch ----------------
__device__ __align__(1024) bf g_xh[Bb*Tt*Cc],  g_xl[Bb*Tt*Cc];
__device__ __align__(1024) bf g_Qh[Bb*Tt*Ee],  g_Ql[Bb*Tt*Ee];
__device__ __align__(1024) bf g_Kh[Bb*Tt*Ee],  g_Kl[Bb*Tt*Ee];
__device__ __align__(1024) bf g_Vth[Bb*Ee*Tt], g_Vtl[Bb*Ee*Tt];
__device__ __align__(1024) bf g_Wqh[Ee*Cc],    g_Wql[Ee*Cc];
__device__ __align__(1024) bf g_Wkh[Ee*Cc],    g_Wkl[Ee*Cc];
__device__ __align__(1024) bf g_Wvh[Ee*Cc],    g_Wvl[Ee*Cc];
__device__ __align__(1024) bf g_Woh[Ee*Ee],    g_Wol[Ee*Ee];
__device__ __align__(1024) bf g_ph[Ff*Dd],     g_pl[Ff*Dd];
__device__ __align__(1024) bf g_Kpth[Bb*Hh*Ff*Tt], g_Kptl[Bb*Hh*Ff*Tt];
__device__ __align__(1024) bf g_ah[Bb*Tt*Ee],  g_al[Bb*Tt*Ee];
__device__ __align__(1024) bf g_KVth[Bb*Hh*64*Ff], g_KVtl[Bb*Hh*64*Ff];
__device__ float g_KVt[Bb*Hh*64*Ff];
__device__ float g_Ksum[Bb*Hh*Ff];
__device__ unsigned g_c0, g_c1;

// ================= PTX helpers =================
__device__ __forceinline__ uint32_t s2u(const void* p){
    uint32_t a;
    asm("{ .reg .u64 t; cvta.to.shared.u64 t, %1; cvt.u32.u64 %0, t; }" : "=r"(a) : "l"(p));
    return a;
}
__device__ __forceinline__ uint32_t swz(uint32_t off){ return off ^ ((off >> 3) & 0x70); }

__device__ __forceinline__ void ldsm4(uint32_t& r0, uint32_t& r1, uint32_t& r2, uint32_t& r3, uint32_t addr){
    asm volatile("ldmatrix.sync.aligned.m8n8.x4.shared.b16 {%0,%1,%2,%3}, [%4];"
        : "=r"(r0), "=r"(r1), "=r"(r2), "=r"(r3) : "r"(addr));
}
__device__ __forceinline__ void mma_bf16(float* c, const uint32_t* a, const uint32_t* b){
    asm volatile("mma.sync.aligned.m16n8k16.row.col.f32.bf16.bf16.f32 "
        "{%0,%1,%2,%3}, {%4,%5,%6,%7}, {%8,%9}, {%0,%1,%2,%3};"
        : "+f"(c[0]), "+f"(c[1]), "+f"(c[2]), "+f"(c[3])
        : "r"(a[0]), "r"(a[1]), "r"(a[2]), "r"(a[3]), "r"(b[0]), "r"(b[1]));
}
__device__ __forceinline__ void cpa16(uint32_t s, const void* g){
    asm volatile("cp.async.cg.shared.global [%0], [%1], 16;" :: "r"(s), "l"(g));
}
__device__ __forceinline__ void cpa_commit(){ asm volatile("cp.async.commit_group;" ::: "memory"); }
__device__ __forceinline__ void cpa_wait0(){ asm volatile("cp.async.wait_group 0;" ::: "memory"); }
__device__ __forceinline__ void cpa_wait1(){ asm volatile("cp.async.wait_group 1;" ::: "memory"); }
__device__ __forceinline__ void cpa_wait2(){ asm volatile("cp.async.wait_group 2;" ::: "memory"); }

__device__ __forceinline__ void split2(float a, bf& h, bf& l){
    h = __float2bfloat16(a);
    l = __float2bfloat16(a - __bfloat162float(h));
}

// ================= small kernels =================
__global__ void k_prep_proj(const float* __restrict__ proj){
    int i = blockIdx.x * 256 + threadIdx.x;
    if (i == 0){ g_c0 = 0; g_c1 = 0; }
    if (i < Ff*Dd){ bf hi, lo; split2(proj[i], hi, lo); g_ph[i] = hi; g_pl[i] = lo; }
    if (i < Bb*Hh*64*Ff) g_KVt[i] = 0.f;
    if (i < Bb*Hh*Ff)    g_Ksum[i] = 0.f;
}
__global__ void k_prep_x(const float* __restrict__ x, float* __restrict__ out){
    __shared__ float tile[32][33];
    int b = blockIdx.z, t0 = blockIdx.x*32, c0 = blockIdx.y*32;
    int tx = threadIdx.x, ty = threadIdx.y;
    for (int i = ty; i < 32; i += 8){
        float v = x[((size_t)b*Cc + c0 + i)*Tt + t0 + tx];
        tile[i][tx] = v;
        out[((size_t)b*CO + c0 + i)*Tt + t0 + tx] = v;
    }
    __syncthreads();
    for (int i = ty; i < 32; i += 8){
        bf hi, lo; split2(tile[tx][i], hi, lo);
        size_t o = ((size_t)b*Tt + t0 + i)*Cc + c0 + tx;
        g_xh[o] = hi; g_xl[o] = lo;
    }
}
__global__ void k_prep_w(const float* __restrict__ Wq, const float* __restrict__ Wk,
                         const float* __restrict__ Wv, const float* __restrict__ Wo){
    const int Nd = Ee;
    int z = blockIdx.z;
    int Kd = (z == 3) ? Ee : Cc;
    int k0 = blockIdx.y*32;
    if (k0 >= Kd) return;
    const float* W = z == 0 ? Wq : z == 1 ? Wk : z == 2 ? Wv : Wo;
    bf* Dh = z == 0 ? g_Wqh : z == 1 ? g_Wkh : z == 2 ? g_Wvh : g_Woh;
    bf* Dl = z == 0 ? g_Wql : z == 1 ? g_Wkl : z == 2 ? g_Wvl : g_Wol;
    __shared__ float tile[32][33];
    int n0 = blockIdx.x*32;
    int tx = threadIdx.x, ty = threadIdx.y;
    for (int i = ty; i < 32; i += 8)
        tile[i][tx] = W[(size_t)(k0 + i)*Nd + n0 + tx];
    __syncthreads();
    for (int i = ty; i < 32; i += 8){
        bf hi, lo; split2(tile[tx][i], hi, lo);
        size_t o = (size_t)(n0 + i)*Kd + k0 + tx;
        Dh[o] = hi; Dl[o] = lo;
    }
}
__global__ void k_cvt_kv(){
    int i = blockIdx.x * 256 + threadIdx.x;
    if (i < Bb*Hh*64*Ff){ bf h, l; split2(g_KVt[i], h, l); g_KVth[i] = h; g_KVtl[i] = l; }
}

// ================= tile loaders =================
template<int NROWS>
__device__ __forceinline__ void load_tileN(uint32_t sbase, const bf* g, int row0, int stride, int k0, int tid){
#pragma unroll
    for (int i = 0; i < NROWS/32; i++){
        int idx = tid + i*256;
        int r = idx >> 3, kc = idx & 7;
        cpa16(sbase + swz((uint32_t)(r*128 + kc*16)), g + (size_t)(row0 + r)*stride + k0 + kc*8);
    }
}

#define STAGE_BYTES 65536

// ================= persistent GEMM: 128x128 tile, 64x32 warp tiles (R14 winner) =================
#define PERS_DSM (3*STAGE_BYTES + 16512)

template<int MODE>
__global__ __launch_bounds__(256, 1) void k_mmaP(float* __restrict__ outp){
    constexpr int NKT   = (MODE == 0) ? 8 : 16;
    constexpr int KA    = (MODE == 0) ? Cc : Ee;
    constexpr int TOTAL = (MODE == 0) ? 3072 : 1024;

    extern __shared__ __align__(1024) char dsm[];
    float* fb = (float*)(dsm + 3*STAGE_BYTES);
    __shared__ int s_cur, s_next;
    uint32_t sb = s2u(dsm);
    int tid = threadIdx.x, lane = tid & 31, w = tid >> 5;
    unsigned* ctr = (MODE == 0) ? &g_c0 : &g_c1;

    if (tid == 0){ s_cur = (int)atomicAdd(ctr, 1u); s_next = (int)atomicAdd(ctr, 1u); }
    __syncthreads();
    int cur = s_cur, nxt = s_next;
    if (cur >= TOTAL) return;

    const bf* Ahp = (MODE == 0) ? g_xh : g_ah;
    const bf* Alp = (MODE == 0) ? g_xl : g_al;

    auto decode = [&](int id, int& rowA, int& rowB, const bf*& Bh2, const bf*& Bl2, int& z){
        if (MODE == 0){
            z = id >> 10; int r = id & 1023;
            rowB = (r >> 7) * 128; rowA = (r & 127) * 128;
            Bh2 = z == 0 ? g_Wqh : z == 1 ? g_Wkh : g_Wvh;
            Bl2 = z == 0 ? g_Wql : z == 1 ? g_Wkl : g_Wvl;
        } else {
            z = 0;
            rowB = (id >> 7) * 128; rowA = (id & 127) * 128;
            Bh2 = g_Woh; Bl2 = g_Wol;
        }
    };
    auto commitStage = [&](int slot, int rA, int rB, const bf* bh, const bf* bl, int k0){
        uint32_t st_ = sb + (uint32_t)slot * STAGE_BYTES;
        load_tileN<128>(st_,         Ahp, rA, KA, k0, tid);
        load_tileN<128>(st_ + 16384, Alp, rA, KA, k0, tid);
        load_tileN<128>(st_ + 32768, bh,  rB, KA, k0, tid);
        load_tileN<128>(st_ + 49152, bl,  rB, KA, k0, tid);
        cpa_commit();
    };

    int rowA, rowB, zc; const bf *Bh2, *Bl2;
    decode(cur, rowA, rowB, Bh2, Bl2, zc);
    commitStage(0, rowA, rowB, Bh2, Bl2, 0);
    commitStage(1, rowA, rowB, Bh2, Bl2, 64);
    int committed = 2, s = 0;

    int rr = lane & 7, sub = lane >> 3;
    int wm = (w & 1) * 64, wn = (w >> 1) * 32;
    int arow = wm + rr + (sub & 1) * 8;
    int acb0 = (sub >> 1) * 16;
    int brow = wn + rr + (sub >> 1) * 8;
    int bcb0 = (sub & 1) * 16;
    int r0row = lane >> 2, c0 = (lane & 3) * 2;

    while (true){
        float acc[4][4][4];
#pragma unroll
        for (int i = 0; i < 4; i++)
#pragma unroll
            for (int j = 0; j < 4; j++)
#pragma unroll
                for (int c = 0; c < 4; c++) acc[i][j][c] = 0.f;

        for (int kt = 0; kt < NKT; kt++){
            int allowed = committed - s - 1;
            if (allowed >= 2) cpa_wait2(); else if (allowed == 1) cpa_wait1(); else cpa_wait0();
            __syncthreads();

            int kt2 = kt + 2;
            if (kt2 < NKT){
                commitStage((s + 2) % 3, rowA, rowB, Bh2, Bl2, kt2*64); committed++;
            } else if (nxt < TOTAL){
                int rA2, rB2, z2; const bf *bh2, *bl2;
                decode(nxt, rA2, rB2, bh2, bl2, z2);
                commitStage((s + 2) % 3, rA2, rB2, bh2, bl2, (kt2 - NKT)*64); committed++;
            }

            uint32_t st = sb + (uint32_t)(s % 3) * STAGE_BYTES;
#pragma unroll
            for (int ks = 0; ks < 4; ks++){
                uint32_t ahf[4][4], alf[4][4], bhf[4][2], blf[4][2];
#pragma unroll
                for (int i = 0; i < 4; i++){
                    uint32_t sa = swz((uint32_t)((arow + i*16)*128 + acb0 + ks*32));
                    ldsm4(ahf[i][0], ahf[i][1], ahf[i][2], ahf[i][3], st + sa);
                    ldsm4(alf[i][0], alf[i][1], alf[i][2], alf[i][3], st + 16384 + sa);
                }
#pragma unroll
                for (int j2 = 0; j2 < 2; j2++){
                    uint32_t sa = swz((uint32_t)((brow + j2*16)*128 + bcb0 + ks*32));
                    uint32_t r0, r1, r2, r3;
                    ldsm4(r0, r1, r2, r3, st + 32768 + sa);
                    bhf[j2*2][0] = r0; bhf[j2*2][1] = r1; bhf[j2*2+1][0] = r2; bhf[j2*2+1][1] = r3;
                    ldsm4(r0, r1, r2, r3, st + 49152 + sa);
                    blf[j2*2][0] = r0; blf[j2*2][1] = r1; blf[j2*2+1][0] = r2; blf[j2*2+1][1] = r3;
                }
#pragma unroll
                for (int i = 0; i < 4; i++)
#pragma unroll
                    for (int j = 0; j < 4; j++){
                        mma_bf16(acc[i][j], ahf[i], bhf[j]);
                        mma_bf16(acc[i][j], ahf[i], blf[j]);
                        mma_bf16(acc[i][j], alf[i], bhf[j]);
                    }
            }
            s++;
        }

        int m0 = rowA, n0 = rowB;
        if (MODE == 0 && zc < 2){
            bf* Dh = zc ? g_Kh : g_Qh;
            bf* Dl = zc ? g_Kl : g_Ql;
#pragma unroll
            for (int i = 0; i < 4; i++)
#pragma unroll
                for (int j = 0; j < 4; j++)
#pragma unroll
                    for (int half = 0; half < 2; half++){
                        int row = m0 + wm + i*16 + r0row + half*8;
                        int col = n0 + wn + j*8 + c0;
                        bf h0, l0, h1, l1;
                        split2(acc[i][j][half*2], h0, l0);
                        split2(acc[i][j][half*2 + 1], h1, l1);
                        *(__nv_bfloat162*)&Dh[(size_t)row*Ee + col] = __nv_bfloat162{h0, h1};
                        *(__nv_bfloat162*)&Dl[(size_t)row*Ee + col] = __nv_bfloat162{l0, l1};
                    }
        } else {
            int b = m0 / Tt, t0 = m0 % Tt;
            __syncthreads();
#pragma unroll
            for (int p = 0; p < 4; p++){
                if ((w & 1) == (p >> 1)){
                    int ibase = (p & 1) * 2;
#pragma unroll
                    for (int ii = 0; ii < 2; ii++)
#pragma unroll
                        for (int j = 0; j < 4; j++)
#pragma unroll
                            for (int half = 0; half < 2; half++){
                                int row = (ibase + ii)*16 + r0row + half*8 - (p & 1)*32;
                                int col = wn + j*8 + c0;
                                fb[row*129 + col]     = acc[ibase + ii][j][half*2];
                                fb[row*129 + col + 1] = acc[ibase + ii][j][half*2 + 1];
                            }
                }
                __syncthreads();
                if (MODE == 0){
                    for (int idx = tid; idx < 4096; idx += 256){
                        int n = idx >> 5, t = idx & 31;
                        bf h, l; split2(fb[t*129 + n], h, l);
                        size_t o = (size_t)(b*Ee + n0 + n)*Tt + t0 + p*32 + t;
                        g_Vth[o] = h; g_Vtl[o] = l;
                    }
                } else {
                    for (int idx = tid; idx < 4096; idx += 256){
                        int n = idx >> 5, t = idx & 31;
                        outp[(size_t)b*CO*Tt + (size_t)(Cc + n0 + n)*Tt + t0 + p*32 + t] = fb[t*129 + n];
                    }
                }
                __syncthreads();
            }
        }

        if (nxt >= TOTAL) break;
        cur = nxt;
        decode(cur, rowA, rowB, Bh2, Bl2, zc);
        if (tid == 0) s_next = (int)atomicAdd(ctr, 1u);
        __syncthreads();
        nxt = s_next;
    }
}

// ================= k_featK: Kp = __expf(K@proj^T)+eps -> transposed split gmem + Ksum =================
#define FEATK_DSM (32768 + 65536 + 66048)

__global__ __launch_bounds__(256, 1) void k_featK(){
    extern __shared__ __align__(1024) char dsm[];
    uint32_t sb = s2u(dsm);
    int tid = threadIdx.x, lane = tid & 31, w = tid >> 5;
    int bh = blockIdx.z;
    int m0 = blockIdx.x * 512, n0 = blockIdx.y * 128;
    const bf* Ah = g_Kh + (bh & 15)*Dd;
    const bf* Al = g_Kl + (bh & 15)*Dd;
    int rowBase = (bh >> 4)*Tt + m0;

    load_tileN<128>(sb,         g_ph, n0, Dd, 0, tid);
    load_tileN<128>(sb + 16384, g_pl, n0, Dd, 0, tid);
    load_tileN<128>(sb + 32768,         Ah, rowBase, Ee, 0, tid);
    load_tileN<128>(sb + 32768 + 16384, Al, rowBase, Ee, 0, tid);
    cpa_commit();
    load_tileN<128>(sb + 65536,         Ah, rowBase + 128, Ee, 0, tid);
    load_tileN<128>(sb + 65536 + 16384, Al, rowBase + 128, Ee, 0, tid);
    cpa_commit();

    int rr = lane & 7, sub = lane >> 3;
    int wm = (w & 1) * 64, wn = (w >> 1) * 32;
    int arow = wm + rr + (sub & 1) * 8;
    int acb0 = (sub >> 1) * 16;
    int brow = wn + rr + (sub >> 1) * 8;
    int bcb0 = (sub & 1) * 16;
    float* fb = (float*)(dsm + 32768 + 65536);

    for (int it = 0; it < 4; it++){
        uint32_t stA = sb + 32768 + (uint32_t)(it & 1) * 32768;
        if (it < 3) cpa_wait1(); else cpa_wait0();
        __syncthreads();

        float acc[4][4][4];
#pragma unroll
        for (int i = 0; i < 4; i++)
#pragma unroll
            for (int j = 0; j < 4; j++)
#pragma unroll
                for (int c = 0; c < 4; c++) acc[i][j][c] = 0.f;

#pragma unroll
        for (int ks = 0; ks < 4; ks++){
            uint32_t ahf[4][4], alf[4][4], bhf[4][2], blf[4][2];
#pragma unroll
            for (int i = 0; i < 4; i++){
                uint32_t sa = swz((uint32_t)((arow + i*16)*128 + acb0 + ks*32));
                ldsm4(ahf[i][0], ahf[i][1], ahf[i][2], ahf[i][3], stA + sa);
                ldsm4(alf[i][0], alf[i][1], alf[i][2], alf[i][3], stA + 16384 + sa);
            }
#pragma unroll
            for (int j2 = 0; j2 < 2; j2++){
                uint32_t sa = swz((uint32_t)((brow + j2*16)*128 + bcb0 + ks*32));
                uint32_t r0, r1, r2, r3;
                ldsm4(r0, r1, r2, r3, sb + sa);
                bhf[j2*2][0] = r0; bhf[j2*2][1] = r1; bhf[j2*2+1][0] = r2; bhf[j2*2+1][1] = r3;
                ldsm4(r0, r1, r2, r3, sb + 16384 + sa);
                blf[j2*2][0] = r0; blf[j2*2][1] = r1; blf[j2*2+1][0] = r2; blf[j2*2+1][1] = r3;
            }
#pragma unroll
            for (int i = 0; i < 4; i++)
#pragma unroll
                for (int j = 0; j < 4; j++){
                    mma_bf16(acc[i][j], ahf[i], bhf[j]);
                    mma_bf16(acc[i][j], ahf[i], blf[j]);
                    mma_bf16(acc[i][j], alf[i], bhf[j]);
                }
        }
        __syncthreads();
        if (it + 2 < 4){
            load_tileN<128>(stA,         Ah, rowBase + (it + 2)*128, Ee, 0, tid);
            load_tileN<128>(stA + 16384, Al, rowBase + (it + 2)*128, Ee, 0, tid);
            cpa_commit();
        }

        int r0row = lane >> 2, c0 = (lane & 3) * 2;
        int mt = it * 128;
#pragma unroll
        for (int i = 0; i < 4; i++)
#pragma unroll
            for (int j = 0; j < 4; j++)
#pragma unroll
                for (int half = 0; half < 2; half++){
                    int row = wm + i*16 + r0row + half*8;
                    int col = wn + j*8 + c0;
                    fb[row*129 + col]     = __expf(acc[i][j][half*2]) + EPS;
                    fb[row*129 + col + 1] = __expf(acc[i][j][half*2 + 1]) + EPS;
                }
        __syncthreads();
        for (int idx = tid; idx < 16384; idx += 256){
            int f = idx >> 7, t = idx & 127;
            bf h, l; split2(fb[t*129 + f], h, l);
            size_t o = (size_t)(bh*Ff + n0 + f)*Tt + m0 + mt + t;
            g_Kpth[o] = h; g_Kptl[o] = l;
        }
        {
            int f = tid >> 1, th = tid & 1;
            float s = 0.f;
#pragma unroll 8
            for (int t = th*64; t < th*64 + 64; t++) s += fb[t*129 + f];
            atomicAdd(&g_Ksum[bh*Ff + n0 + f], s);
        }
        __syncthreads();
    }
}

// ================= k_kv: KV += Kp^T @ V^T over 512-T chunks =================
#define MMA_DSM 196608

__global__ __launch_bounds__(256, 1) void k_kv(){
    constexpr int NKT = 8;
    extern __shared__ __align__(1024) char dsm[];
    uint32_t sb = s2u(dsm);
    int tid = threadIdx.x, lane = tid & 31, w = tid >> 5;
    int bz = blockIdx.z;
    int m0 = blockIdx.x * 128;

    const bf* Ahp = g_Kpth;
    const bf* Alp = g_Kptl;
    int rowA0 = bz*Ff + m0;
    int rowB0 = (bz >> 4)*Ee + (bz & 15)*Dd;
    int k0base = blockIdx.y * 512;

    float acc[4][2][4];
#pragma unroll
    for (int i = 0; i < 4; i++)
#pragma unroll
        for (int j = 0; j < 2; j++)
#pragma unroll
            for (int c = 0; c < 4; c++) acc[i][j][c] = 0.f;

#define LOADSTG(s, k0) do { \
        uint32_t st_ = sb + (uint32_t)(s)*STAGE_BYTES; \
        load_tileN<128>(st_,         Ahp, rowA0, Tt, (k0), tid); \
        load_tileN<128>(st_ + 16384, Alp, rowA0, Tt, (k0), tid); \
        load_tileN<64>(st_ + 32768,  g_Vth, rowB0, Tt, (k0), tid); \
        load_tileN<64>(st_ + 40960,  g_Vtl, rowB0, Tt, (k0), tid); \
        cpa_commit(); \
    } while(0)

    LOADSTG(0, k0base);
    LOADSTG(1, k0base + 64);
    int committed = 2;

    int rr = lane & 7, sub = lane >> 3;
    int wm = (w & 1) * 64, wn = (w >> 1) * 16;
    int arow = wm + rr + (sub & 1) * 8;
    int acb0 = (sub >> 1) * 16;
    int brow = wn + rr + (sub >> 1) * 8;
    int bcb0 = (sub & 1) * 16;

    for (int kt = 0; kt < NKT; kt++){
        int allowed = committed - kt - 1;
        if (allowed >= 2) cpa_wait2(); else if (allowed == 1) cpa_wait1(); else cpa_wait0();
        __syncthreads();
        if (kt + 2 < NKT){ LOADSTG((kt + 2) % 3, k0base + (kt + 2)*64); committed++; }

        uint32_t st = sb + (uint32_t)(kt % 3) * STAGE_BYTES;
#pragma unroll
        for (int ks = 0; ks < 4; ks++){
            uint32_t ahf[4][4], alf[4][4], bhf[2][2], blf[2][2];
#pragma unroll
            for (int i = 0; i < 4; i++){
                uint32_t sa = swz((uint32_t)((arow + i*16)*128 + acb0 + ks*32));
                ldsm4(ahf[i][0], ahf[i][1], ahf[i][2], ahf[i][3], st + sa);
                ldsm4(alf[i][0], alf[i][1], alf[i][2], alf[i][3], st + 16384 + sa);
            }
            {
                uint32_t sa = swz((uint32_t)(brow*128 + bcb0 + ks*32));
                uint32_t r0, r1, r2, r3;
                ldsm4(r0, r1, r2, r3, st + 32768 + sa);
                bhf[0][0] = r0; bhf[0][1] = r1; bhf[1][0] = r2; bhf[1][1] = r3;
                ldsm4(r0, r1, r2, r3, st + 40960 + sa);
                blf[0][0] = r0; blf[0][1] = r1; blf[1][0] = r2; blf[1][1] = r3;
            }
#pragma unroll
            for (int i = 0; i < 4; i++)
#pragma unroll
                for (int j = 0; j < 2; j++){
                    mma_bf16(acc[i][j], ahf[i], bhf[j]);
                    mma_bf16(acc[i][j], ahf[i], blf[j]);
                    mma_bf16(acc[i][j], alf[i], bhf[j]);
                }
        }
    }
#undef LOADSTG

    int r0row = lane >> 2, c0 = (lane & 3) * 2;
    float* fb = (float*)dsm;
    __syncthreads();
#pragma unroll
    for (int i = 0; i < 4; i++)
#pragma unroll
        for (int j = 0; j < 2; j++)
#pragma unroll
            for (int half = 0; half < 2; half++){
                int row = wm + i*16 + r0row + half*8;
                int col = wn + j*8 + c0;
                fb[row*129 + col]     = acc[i][j][half*2];
                fb[row*129 + col + 1] = acc[i][j][half*2 + 1];
            }
    __syncthreads();
    for (int idx = tid; idx < 8192; idx += 256){
        int n = idx >> 7, f = idx & 127;
        atomicAdd(&g_KVt[((size_t)bz*64 + n)*Ff + m0 + f], fb[f*129 + n]);
    }
}

// ================= k_fattn: fused Qp + attn (R14 winner, __expf) =================
#define FA_KVH   0
#define FA_KVL   32768
#define FA_QH    65536
#define FA_QL    81920
#define FA_PJH   98304
#define FA_PJL   131072
#define FA_QPH   163840
#define FA_QPL   196608
#define FA_DEN   229376
#define FA_KS    229888
#define FATTN_DSM 230912

__global__ __launch_bounds__(256, 1) void k_fattn(){
    extern __shared__ __align__(1024) char dsm[];
    uint32_t sb = s2u(dsm);
    float* sden = (float*)(dsm + FA_DEN);
    float* sKs  = (float*)(dsm + FA_KS);
    int tid = threadIdx.x, lane = tid & 31, w = tid >> 5;
    int bh = blockIdx.z;
    int t0 = blockIdx.x * 128;
    int b = bh >> 4, h = bh & 15;
    int qrow0 = b*Tt + t0;
    int kvrow0 = bh*64;

    if (tid < 128) sden[tid] = 0.f;
    sKs[tid] = g_Ksum[bh*Ff + tid];

#pragma unroll
    for (int i = 0; i < 8; i++){
        int idx = tid + i*256;
        int ch = idx >> 9, r = (idx >> 3) & 63, kc = idx & 7;
        uint32_t sa = (uint32_t)(ch*8192) + swz((uint32_t)(r*128 + kc*16));
        cpa16(sb + FA_KVH + sa, g_KVth + (size_t)(kvrow0 + r)*Ff + ch*64 + kc*8);
        cpa16(sb + FA_KVL + sa, g_KVtl + (size_t)(kvrow0 + r)*Ff + ch*64 + kc*8);
    }
    load_tileN<128>(sb + FA_QH, g_Qh + h*Dd, qrow0, Ee, 0, tid);
    load_tileN<128>(sb + FA_QL, g_Ql + h*Dd, qrow0, Ee, 0, tid);
    load_tileN<256>(sb + FA_PJH, g_ph, 0, Dd, 0, tid);
    load_tileN<256>(sb + FA_PJL, g_pl, 0, Dd, 0, tid);
    cpa_commit();
    cpa_wait0();
    __syncthreads();

    int rr = lane & 7, sub = lane >> 3;
    int wm = (w & 1) * 64;
    int wn = (w >> 1) * 32;
    int wn2 = (w >> 1) * 16;
    int arow = wm + rr + (sub & 1) * 8;
    int acb0 = (sub >> 1) * 16;
    int brow = wn + rr + (sub >> 1) * 8;
    int bcb0 = (sub & 1) * 16;
    int brow2 = wn2 + rr + (sub >> 1) * 8;
    int r0row = lane >> 2, c0 = (lane & 3) * 2;

    float acc2[4][2][4];
#pragma unroll
    for (int i = 0; i < 4; i++)
#pragma unroll
        for (int j = 0; j < 2; j++)
#pragma unroll
            for (int c = 0; c < 4; c++) acc2[i][j][c] = 0.f;

    for (int fh = 0; fh < 2; fh++){
        float acc[4][4][4];
#pragma unroll
        for (int i = 0; i < 4; i++)
#pragma unroll
            for (int j = 0; j < 4; j++)
#pragma unroll
                for (int c = 0; c < 4; c++) acc[i][j][c] = 0.f;
#pragma unroll
        for (int ks = 0; ks < 4; ks++){
            uint32_t ahf[4][4], alf[4][4], bhf[4][2], blf[4][2];
#pragma unroll
            for (int i = 0; i < 4; i++){
                uint32_t sa = swz((uint32_t)((arow + i*16)*128 + acb0 + ks*32));
                ldsm4(ahf[i][0], ahf[i][1], ahf[i][2], ahf[i][3], sb + FA_QH + sa);
                ldsm4(alf[i][0], alf[i][1], alf[i][2], alf[i][3], sb + FA_QL + sa);
            }
#pragma unroll
            for (int j2 = 0; j2 < 2; j2++){
                uint32_t sa = (uint32_t)(fh*16384) + swz((uint32_t)((brow + j2*16)*128 + bcb0 + ks*32));
                uint32_t r0, r1, r2, r3;
                ldsm4(r0, r1, r2, r3, sb + FA_PJH + sa);
                bhf[j2*2][0] = r0; bhf[j2*2][1] = r1; bhf[j2*2+1][0] = r2; bhf[j2*2+1][1] = r3;
                ldsm4(r0, r1, r2, r3, sb + FA_PJL + sa);
                blf[j2*2][0] = r0; blf[j2*2][1] = r1; blf[j2*2+1][0] = r2; blf[j2*2+1][1] = r3;
            }
#pragma unroll
            for (int i = 0; i < 4; i++)
#pragma unroll
                for (int j = 0; j < 4; j++){
                    mma_bf16(acc[i][j], ahf[i], bhf[j]);
                    mma_bf16(acc[i][j], ahf[i], blf[j]);
                    mma_bf16(acc[i][j], alf[i], bhf[j]);
                }
        }

        float dloc[8];
#pragma unroll
        for (int e = 0; e < 8; e++) dloc[e] = 0.f;
#pragma unroll
        for (int i = 0; i < 4; i++)
#pragma unroll
            for (int j = 0; j < 4; j++)
#pragma unroll
                for (int half = 0; half < 2; half++){
                    int trow = wm + i*16 + r0row + half*8;
                    int f0 = wn + j*8 + c0;
                    float v0 = __expf(acc[i][j][half*2]) + EPS;
                    float v1 = __expf(acc[i][j][half*2 + 1]) + EPS;
                    dloc[i*2 + half] += v0 * sKs[fh*128 + f0] + v1 * sKs[fh*128 + f0 + 1];
                    bf h0, l0, h1, l1;
                    split2(v0, h0, l0); split2(v1, h1, l1);
                    uint32_t addr = (uint32_t)((f0 >> 6)*16384) + swz((uint32_t)(trow*128 + (f0 & 63)*2));
                    *(__nv_bfloat162*)(dsm + FA_QPH + addr) = __nv_bfloat162{h0, h1};
                    *(__nv_bfloat162*)(dsm + FA_QPL + addr) = __nv_bfloat162{l0, l1};
                }
#pragma unroll
        for (int e = 0; e < 8; e++){
            float v = dloc[e];
            v += __shfl_xor_sync(0xffffffffu, v, 1);
            v += __shfl_xor_sync(0xffffffffu, v, 2);
            if ((lane & 3) == 0)
                atomicAdd(&sden[wm + (e >> 1)*16 + r0row + (e & 1)*8], v);
        }
        __syncthreads();

#pragma unroll
        for (int kc = 0; kc < 2; kc++){
            uint32_t qa = FA_QPH + (uint32_t)kc*16384;
            uint32_t ql = FA_QPL + (uint32_t)kc*16384;
            uint32_t va = FA_KVH + (uint32_t)(fh*2 + kc)*8192;
            uint32_t vl = FA_KVL + (uint32_t)(fh*2 + kc)*8192;
#pragma unroll
            for (int ks = 0; ks < 4; ks++){
                uint32_t ahf[4][4], alf[4][4], bhf[2][2], blf[2][2];
#pragma unroll
                for (int i = 0; i < 4; i++){
                    uint32_t sa = swz((uint32_t)((arow + i*16)*128 + acb0 + ks*32));
                    ldsm4(ahf[i][0], ahf[i][1], ahf[i][2], ahf[i][3], sb + qa + sa);
                    ldsm4(alf[i][0], alf[i][1], alf[i][2], alf[i][3], sb + ql + sa);
                }
                {
                    uint32_t sa = swz((uint32_t)(brow2*128 + bcb0 + ks*32));
                    uint32_t r0, r1, r2, r3;
                    ldsm4(r0, r1, r2, r3, sb + va + sa);
                    bhf[0][0] = r0; bhf[0][1] = r1; bhf[1][0] = r2; bhf[1][1] = r3;
                    ldsm4(r0, r1, r2, r3, sb + vl + sa);
                    blf[0][0] = r0; blf[0][1] = r1; blf[1][0] = r2; blf[1][1] = r3;
                }
#pragma unroll
                for (int i = 0; i < 4; i++)
#pragma unroll
                    for (int j = 0; j < 2; j++){
                        mma_bf16(acc2[i][j], ahf[i], bhf[j]);
                        mma_bf16(acc2[i][j], ahf[i], blf[j]);
                        mma_bf16(acc2[i][j], alf[i], bhf[j]);
                    }
            }
        }
        if (fh == 0) __syncthreads();
    }

    __syncthreads();
#pragma unroll
    for (int i = 0; i < 4; i++)
#pragma unroll
        for (int half = 0; half < 2; half++){
            int row = wm + i*16 + r0row + half*8;
            float inv = 1.0f / fmaxf(sden[row], 1e-6f);
#pragma unroll
            for (int j = 0; j < 2; j++){
                int col = wn2 + j*8 + c0;
                bf h0, l0, h1, l1;
                split2(acc2[i][j][half*2] * inv, h0, l0);
                split2(acc2[i][j][half*2 + 1] * inv, h1, l1);
                size_t o = (size_t)(b*Tt + t0 + row)*Ee + h*Dd + col;
                *(__nv_bfloat162*)&g_ah[o] = __nv_bfloat162{h0, h1};
                *(__nv_bfloat162*)&g_al[o] = __nv_bfloat162{l0, l1};
            }
        }
}

// ================= launch =================
extern "C" void kernel_launch(void* const* d_in, const int* in_sizes, int n_in,
                              void* d_out, int out_size) {
    const float* x    = (const float*)d_in[0];
    const float* Wq   = (const float*)d_in[1];
    const float* Wk   = (const float*)d_in[2];
    const float* Wv   = (const float*)d_in[3];
    const float* Wo   = (const float*)d_in[4];
    const float* proj = (const float*)d_in[5];
    float* out = (float*)d_out;

    cudaFuncSetAttribute(k_mmaP<0>, cudaFuncAttributeMaxDynamicSharedMemorySize, PERS_DSM);
    cudaFuncSetAttribute(k_mmaP<1>, cudaFuncAttributeMaxDynamicSharedMemorySize, PERS_DSM);
    cudaFuncSetAttribute(k_featK,   cudaFuncAttributeMaxDynamicSharedMemorySize, FEATK_DSM);
    cudaFuncSetAttribute(k_kv,      cudaFuncAttributeMaxDynamicSharedMemorySize, MMA_DSM);
    cudaFuncSetAttribute(k_fattn,   cudaFuncAttributeMaxDynamicSharedMemorySize, FATTN_DSM);

    k_prep_proj<<<(Bb*Hh*64*Ff + 255)/256, 256>>>(proj);
    k_prep_x<<<dim3(Tt/32, Cc/32, Bb), dim3(32, 8)>>>(x, out);
    k_prep_w<<<dim3(Ee/32, Ee/32, 4), dim3(32, 8)>>>(Wq, Wk, Wv, Wo);

    k_mmaP<0><<<148, 256, PERS_DSM>>>(nullptr);                            // QKV (persistent)
    k_featK<<<dim3(Tt/512, Ff/128, Bb*Hh), 256, FEATK_DSM>>>();            // Kp + Ksum
    k_kv<<<dim3(Ff/128, 8, Bb*Hh), 256, MMA_DSM>>>();                      // KV
    k_cvt_kv<<<(Bb*Hh*64*Ff + 255)/256, 256>>>();
    k_fattn<<<dim3(Tt/128, 1, Bb*Hh), 256, FATTN_DSM>>>();                 // Qp + attn (fused)
    k_mmaP<1><<<148, 256, PERS_DSM>>>(out);                                // Wo + concat (persistent)
}

// round 17
// speedup vs baseline: 1.1212x; 1.0802x over previous
#include <cuda_runtime.h>
#include <cuda_bf16.h>
#include <cstdint>
#include <math.h>

#define Bb 4
#define Cc 512
#define Tt 4096
#define Ee 1024
#define Hh 16
#define Dd 64
#define Ff 256
#define CO 1536
#define EPS 1e-6f

typedef __nv_bfloat16 bf;

// ---------------- scratch ----------------
__device__ __align__(1024) bf g_xh[Bb*Tt*Cc],  g_xl[Bb*Tt*Cc];
__device__ __align__(1024) bf g_Qh[Bb*Tt*Ee],  g_Ql[Bb*Tt*Ee];
__device__ __align__(1024) bf g_Kh[Bb*Tt*Ee],  g_Kl[Bb*Tt*Ee];
__device__ __align__(1024) bf g_Vth[Bb*Ee*Tt], g_Vtl[Bb*Ee*Tt];
__device__ __align__(1024) bf g_Wqh[Ee*Cc],    g_Wql[Ee*Cc];
__device__ __align__(1024) bf g_Wkh[Ee*Cc],    g_Wkl[Ee*Cc];
__device__ __align__(1024) bf g_Wvh[Ee*Cc],    g_Wvl[Ee*Cc];
__device__ __align__(1024) bf g_Woh[Ee*Ee],    g_Wol[Ee*Ee];
__device__ __align__(1024) bf g_ph[Ff*Dd],     g_pl[Ff*Dd];
__device__ __align__(1024) bf g_ah[Bb*Tt*Ee],  g_al[Bb*Tt*Ee];
__device__ __align__(1024) bf g_KVth[Bb*Hh*64*Ff], g_KVtl[Bb*Hh*64*Ff];
__device__ float g_KVt[Bb*Hh*64*Ff];
__device__ float g_Ksum[Bb*Hh*Ff];
__device__ unsigned g_c0, g_c1;

// ================= PTX helpers =================
__device__ __forceinline__ uint32_t s2u(const void* p){
    uint32_t a;
    asm("{ .reg .u64 t; cvta.to.shared.u64 t, %1; cvt.u32.u64 %0, t; }" : "=r"(a) : "l"(p));
    return a;
}
__device__ __forceinline__ uint32_t swz(uint32_t off){ return off ^ ((off >> 3) & 0x70); }

__device__ __forceinline__ void ldsm4(uint32_t& r0, uint32_t& r1, uint32_t& r2, uint32_t& r3, uint32_t addr){
    asm volatile("ldmatrix.sync.aligned.m8n8.x4.shared.b16 {%0,%1,%2,%3}, [%4];"
        : "=r"(r0), "=r"(r1), "=r"(r2), "=r"(r3) : "r"(addr));
}
__device__ __forceinline__ void ldsm4t(uint32_t& r0, uint32_t& r1, uint32_t& r2, uint32_t& r3, uint32_t addr){
    asm volatile("ldmatrix.sync.aligned.m8n8.x4.trans.shared.b16 {%0,%1,%2,%3}, [%4];"
        : "=r"(r0), "=r"(r1), "=r"(r2), "=r"(r3) : "r"(addr));
}
__device__ __forceinline__ void mma_bf16(float* c, const uint32_t* a, const uint32_t* b){
    asm volatile("mma.sync.aligned.m16n8k16.row.col.f32.bf16.bf16.f32 "
        "{%0,%1,%2,%3}, {%4,%5,%6,%7}, {%8,%9}, {%0,%1,%2,%3};"
        : "+f"(c[0]), "+f"(c[1]), "+f"(c[2]), "+f"(c[3])
        : "r"(a[0]), "r"(a[1]), "r"(a[2]), "r"(a[3]), "r"(b[0]), "r"(b[1]));
}
__device__ __forceinline__ void cpa16(uint32_t s, const void* g){
    asm volatile("cp.async.cg.shared.global [%0], [%1], 16;" :: "r"(s), "l"(g));
}
__device__ __forceinline__ void cpa_commit(){ asm volatile("cp.async.commit_group;" ::: "memory"); }
__device__ __forceinline__ void cpa_wait0(){ asm volatile("cp.async.wait_group 0;" ::: "memory"); }
__device__ __forceinline__ void cpa_wait1(){ asm volatile("cp.async.wait_group 1;" ::: "memory"); }
__device__ __forceinline__ void cpa_wait2(){ asm volatile("cp.async.wait_group 2;" ::: "memory"); }

__device__ __forceinline__ void split2(float a, bf& h, bf& l){
    h = __float2bfloat16(a);
    l = __float2bfloat16(a - __bfloat162float(h));
}

// ================= small kernels =================
__global__ void k_prep_proj(const float* __restrict__ proj){
    int i = blockIdx.x * 256 + threadIdx.x;
    if (i == 0){ g_c0 = 0; g_c1 = 0; }
    if (i < Ff*Dd){ bf hi, lo; split2(proj[i], hi, lo); g_ph[i] = hi; g_pl[i] = lo; }
    if (i < Bb*Hh*64*Ff) g_KVt[i] = 0.f;
    if (i < Bb*Hh*Ff)    g_Ksum[i] = 0.f;
}
__global__ void k_prep_x(const float* __restrict__ x, float* __restrict__ out){
    __shared__ float tile[32][33];
    int b = blockIdx.z, t0 = blockIdx.x*32, c0 = blockIdx.y*32;
    int tx = threadIdx.x, ty = threadIdx.y;
    for (int i = ty; i < 32; i += 8){
        float v = x[((size_t)b*Cc + c0 + i)*Tt + t0 + tx];
        tile[i][tx] = v;
        out[((size_t)b*CO + c0 + i)*Tt + t0 + tx] = v;
    }
    __syncthreads();
    for (int i = ty; i < 32; i += 8){
        bf hi, lo; split2(tile[tx][i], hi, lo);
        size_t o = ((size_t)b*Tt + t0 + i)*Cc + c0 + tx;
        g_xh[o] = hi; g_xl[o] = lo;
    }
}
__global__ void k_prep_w(const float* __restrict__ Wq, const float* __restrict__ Wk,
                         const float* __restrict__ Wv, const float* __restrict__ Wo){
    const int Nd = Ee;
    int z = blockIdx.z;
    int Kd = (z == 3) ? Ee : Cc;
    int k0 = blockIdx.y*32;
    if (k0 >= Kd) return;
    const float* W = z == 0 ? Wq : z == 1 ? Wk : z == 2 ? Wv : Wo;
    bf* Dh = z == 0 ? g_Wqh : z == 1 ? g_Wkh : z == 2 ? g_Wvh : g_Woh;
    bf* Dl = z == 0 ? g_Wql : z == 1 ? g_Wkl : z == 2 ? g_Wvl : g_Wol;
    __shared__ float tile[32][33];
    int n0 = blockIdx.x*32;
    int tx = threadIdx.x, ty = threadIdx.y;
    for (int i = ty; i < 32; i += 8)
        tile[i][tx] = W[(size_t)(k0 + i)*Nd + n0 + tx];
    __syncthreads();
    for (int i = ty; i < 32; i += 8){
        bf hi, lo; split2(tile[tx][i], hi, lo);
        size_t o = (size_t)(n0 + i)*Kd + k0 + tx;
        Dh[o] = hi; Dl[o] = lo;
    }
}
__global__ void k_cvt_kv(){
    int i = blockIdx.x * 256 + threadIdx.x;
    if (i < Bb*Hh*64*Ff){ bf h, l; split2(g_KVt[i], h, l); g_KVth[i] = h; g_KVtl[i] = l; }
}

// ================= tile loaders =================
template<int NROWS>
__device__ __forceinline__ void load_tileN(uint32_t sbase, const bf* g, int row0, int stride, int k0, int tid){
#pragma unroll
    for (int i = 0; i < NROWS/32; i++){
        int idx = tid + i*256;
        int r = idx >> 3, kc = idx & 7;
        cpa16(sbase + swz((uint32_t)(r*128 + kc*16)), g + (size_t)(row0 + r)*stride + k0 + kc*8);
    }
}

#define STAGE_BYTES 65536

// ================= persistent GEMM: 128x128 tile, 64x32 warp tiles =================
#define PERS_DSM (3*STAGE_BYTES + 16512)

template<int MODE>
__global__ __launch_bounds__(256, 1) void k_mmaP(float* __restrict__ outp){
    constexpr int NKT   = (MODE == 0) ? 8 : 16;
    constexpr int KA    = (MODE == 0) ? Cc : Ee;
    constexpr int TOTAL = (MODE == 0) ? 3072 : 1024;

    extern __shared__ __align__(1024) char dsm[];
    float* fb = (float*)(dsm + 3*STAGE_BYTES);
    __shared__ int s_cur, s_next;
    uint32_t sb = s2u(dsm);
    int tid = threadIdx.x, lane = tid & 31, w = tid >> 5;
    unsigned* ctr = (MODE == 0) ? &g_c0 : &g_c1;

    if (tid == 0){ s_cur = (int)atomicAdd(ctr, 1u); s_next = (int)atomicAdd(ctr, 1u); }
    __syncthreads();
    int cur = s_cur, nxt = s_next;
    if (cur >= TOTAL) return;

    const bf* Ahp = (MODE == 0) ? g_xh : g_ah;
    const bf* Alp = (MODE == 0) ? g_xl : g_al;

    auto decode = [&](int id, int& rowA, int& rowB, const bf*& Bh2, const bf*& Bl2, int& z){
        if (MODE == 0){
            z = id >> 10; int r = id & 1023;
            rowB = (r >> 7) * 128; rowA = (r & 127) * 128;
            Bh2 = z == 0 ? g_Wqh : z == 1 ? g_Wkh : g_Wvh;
            Bl2 = z == 0 ? g_Wql : z == 1 ? g_Wkl : g_Wvl;
        } else {
            z = 0;
            rowB = (id >> 7) * 128; rowA = (id & 127) * 128;
            Bh2 = g_Woh; Bl2 = g_Wol;
        }
    };
    auto commitStage = [&](int slot, int rA, int rB, const bf* bh, const bf* bl, int k0){
        uint32_t st_ = sb + (uint32_t)slot * STAGE_BYTES;
        load_tileN<128>(st_,         Ahp, rA, KA, k0, tid);
        load_tileN<128>(st_ + 16384, Alp, rA, KA, k0, tid);
        load_tileN<128>(st_ + 32768, bh,  rB, KA, k0, tid);
        load_tileN<128>(st_ + 49152, bl,  rB, KA, k0, tid);
        cpa_commit();
    };

    int rowA, rowB, zc; const bf *Bh2, *Bl2;
    decode(cur, rowA, rowB, Bh2, Bl2, zc);
    commitStage(0, rowA, rowB, Bh2, Bl2, 0);
    commitStage(1, rowA, rowB, Bh2, Bl2, 64);
    int committed = 2, s = 0;

    int rr = lane & 7, sub = lane >> 3;
    int wm = (w & 1) * 64, wn = (w >> 1) * 32;
    int arow = wm + rr + (sub & 1) * 8;
    int acb0 = (sub >> 1) * 16;
    int brow = wn + rr + (sub >> 1) * 8;
    int bcb0 = (sub & 1) * 16;
    int r0row = lane >> 2, c0 = (lane & 3) * 2;

    while (true){
        float acc[4][4][4];
#pragma unroll
        for (int i = 0; i < 4; i++)
#pragma unroll
            for (int j = 0; j < 4; j++)
#pragma unroll
                for (int c = 0; c < 4; c++) acc[i][j][c] = 0.f;

        for (int kt = 0; kt < NKT; kt++){
            int allowed = committed - s - 1;
            if (allowed >= 2) cpa_wait2(); else if (allowed == 1) cpa_wait1(); else cpa_wait0();
            __syncthreads();

            int kt2 = kt + 2;
            if (kt2 < NKT){
                commitStage((s + 2) % 3, rowA, rowB, Bh2, Bl2, kt2*64); committed++;
            } else if (nxt < TOTAL){
                int rA2, rB2, z2; const bf *bh2, *bl2;
                decode(nxt, rA2, rB2, bh2, bl2, z2);
                commitStage((s + 2) % 3, rA2, rB2, bh2, bl2, (kt2 - NKT)*64); committed++;
            }

            uint32_t st = sb + (uint32_t)(s % 3) * STAGE_BYTES;
#pragma unroll
            for (int ks = 0; ks < 4; ks++){
                uint32_t ahf[4][4], alf[4][4], bhf[4][2], blf[4][2];
#pragma unroll
                for (int i = 0; i < 4; i++){
                    uint32_t sa = swz((uint32_t)((arow + i*16)*128 + acb0 + ks*32));
                    ldsm4(ahf[i][0], ahf[i][1], ahf[i][2], ahf[i][3], st + sa);
                    ldsm4(alf[i][0], alf[i][1], alf[i][2], alf[i][3], st + 16384 + sa);
                }
#pragma unroll
                for (int j2 = 0; j2 < 2; j2++){
                    uint32_t sa = swz((uint32_t)((brow + j2*16)*128 + bcb0 + ks*32));
                    uint32_t r0, r1, r2, r3;
                    ldsm4(r0, r1, r2, r3, st + 32768 + sa);
                    bhf[j2*2][0] = r0; bhf[j2*2][1] = r1; bhf[j2*2+1][0] = r2; bhf[j2*2+1][1] = r3;
                    ldsm4(r0, r1, r2, r3, st + 49152 + sa);
                    blf[j2*2][0] = r0; blf[j2*2][1] = r1; blf[j2*2+1][0] = r2; blf[j2*2+1][1] = r3;
                }
#pragma unroll
                for (int i = 0; i < 4; i++)
#pragma unroll
                    for (int j = 0; j < 4; j++){
                        mma_bf16(acc[i][j], ahf[i], bhf[j]);
                        mma_bf16(acc[i][j], ahf[i], blf[j]);
                        mma_bf16(acc[i][j], alf[i], bhf[j]);
                    }
            }
            s++;
        }

        int m0 = rowA, n0 = rowB;
        if (MODE == 0 && zc < 2){
            bf* Dh = zc ? g_Kh : g_Qh;
            bf* Dl = zc ? g_Kl : g_Ql;
#pragma unroll
            for (int i = 0; i < 4; i++)
#pragma unroll
                for (int j = 0; j < 4; j++)
#pragma unroll
                    for (int half = 0; half < 2; half++){
                        int row = m0 + wm + i*16 + r0row + half*8;
                        int col = n0 + wn + j*8 + c0;
                        bf h0, l0, h1, l1;
                        split2(acc[i][j][half*2], h0, l0);
                        split2(acc[i][j][half*2 + 1], h1, l1);
                        *(__nv_bfloat162*)&Dh[(size_t)row*Ee + col] = __nv_bfloat162{h0, h1};
                        *(__nv_bfloat162*)&Dl[(size_t)row*Ee + col] = __nv_bfloat162{l0, l1};
                    }
        } else {
            int b = m0 / Tt, t0 = m0 % Tt;
            __syncthreads();
#pragma unroll
            for (int p = 0; p < 4; p++){
                if ((w & 1) == (p >> 1)){
                    int ibase = (p & 1) * 2;
#pragma unroll
                    for (int ii = 0; ii < 2; ii++)
#pragma unroll
                        for (int j = 0; j < 4; j++)
#pragma unroll
                            for (int half = 0; half < 2; half++){
                                int row = (ibase + ii)*16 + r0row + half*8 - (p & 1)*32;
                                int col = wn + j*8 + c0;
                                fb[row*129 + col]     = acc[ibase + ii][j][half*2];
                                fb[row*129 + col + 1] = acc[ibase + ii][j][half*2 + 1];
                            }
                }
                __syncthreads();
                if (MODE == 0){
                    for (int idx = tid; idx < 4096; idx += 256){
                        int n = idx >> 5, t = idx & 31;
                        bf h, l; split2(fb[t*129 + n], h, l);
                        size_t o = (size_t)(b*Ee + n0 + n)*Tt + t0 + p*32 + t;
                        g_Vth[o] = h; g_Vtl[o] = l;
                    }
                } else {
                    for (int idx = tid; idx < 4096; idx += 256){
                        int n = idx >> 5, t = idx & 31;
                        outp[(size_t)b*CO*Tt + (size_t)(Cc + n0 + n)*Tt + t0 + p*32 + t] = fb[t*129 + n];
                    }
                }
                __syncthreads();
            }
        }

        if (nxt >= TOTAL) break;
        cur = nxt;
        decode(cur, rowA, rowB, Bh2, Bl2, zc);
        if (tid == 0) s_next = (int)atomicAdd(ctr, 1u);
        __syncthreads();
        nxt = s_next;
    }
}

// ================= k_featKV: Kp tile computed, KV + Ksum produced; Kp never hits gmem =================
// Block: (512-t chunk, 128-f tile, bh). Per 128-t iteration:
//   feat MMA acc[t][f] -> __expf -> conflict-free [t][f] split store + Ksum partials
//   KV MMA acc2[f][d] += Kp^T @ V^T, A-operand via ldmatrix.trans on the [t][f] buffer.
#define FKV_PJH 0
#define FKV_PJL 16384
#define FKV_KST 32768      // 2 stages x 32K (Kh 16K | Kl 16K)
#define FKV_VST 98304      // 2 stages x 32K (Vh 16K [2 ch of d64xt64] | Vl 16K)
#define FKV_KPH 163840     // 2 chunks (f>>6) x 16K, [t128][f64]
#define FKV_KPL 196608
#define FKV_KS  229376
#define FKV_DSM 229888

__global__ __launch_bounds__(256, 1) void k_featKV(){
    extern __shared__ __align__(1024) char dsm[];
    uint32_t sb = s2u(dsm);
    float* sksum = (float*)(dsm + FKV_KS);
    int tid = threadIdx.x, lane = tid & 31, w = tid >> 5;
    int bh = blockIdx.z;
    int m0 = blockIdx.x * 512, n0 = blockIdx.y * 128;
    const bf* Ah = g_Kh + (bh & 15)*Dd;
    const bf* Al = g_Kl + (bh & 15)*Dd;
    int rowBase = (bh >> 4)*Tt + m0;
    int vrow0 = (bh >> 4)*Ee + (bh & 15)*Dd;

    if (tid < 128) sksum[tid] = 0.f;

    auto loadK = [&](int s, int it){
        uint32_t st = sb + FKV_KST + (uint32_t)s*32768;
        load_tileN<128>(st,         Ah, rowBase + it*128, Ee, 0, tid);
        load_tileN<128>(st + 16384, Al, rowBase + it*128, Ee, 0, tid);
    };
    auto loadV = [&](int s, int it){
        uint32_t st = sb + FKV_VST + (uint32_t)s*32768;
        int tb = m0 + it*128;
#pragma unroll
        for (int i = 0; i < 4; i++){
            int idx = tid + i*256;
            int ch = idx >> 9, r = (idx >> 3) & 63, kc = idx & 7;
            uint32_t sa = (uint32_t)(ch*8192) + swz((uint32_t)(r*128 + kc*16));
            cpa16(st + sa,         g_Vth + (size_t)(vrow0 + r)*Tt + tb + ch*64 + kc*8);
            cpa16(st + 16384 + sa, g_Vtl + (size_t)(vrow0 + r)*Tt + tb + ch*64 + kc*8);
        }
    };

    // prologue: g0 = {proj, K0, V0}, g1 = {K1, V1}
    load_tileN<128>(sb + FKV_PJH, g_ph, n0, Dd, 0, tid);
    load_tileN<128>(sb + FKV_PJL, g_pl, n0, Dd, 0, tid);
    loadK(0, 0); loadV(0, 0); cpa_commit();
    loadK(1, 1); loadV(1, 1); cpa_commit();

    int rr = lane & 7, sub = lane >> 3;
    // feat mapping: m=t, n=f
    int wm = (w & 1) * 64, wn = (w >> 1) * 32;
    int arow = wm + rr + (sub & 1) * 8;
    int acb0 = (sub >> 1) * 16;
    int brow = wn + rr + (sub >> 1) * 8;
    int bcb0 = (sub & 1) * 16;
    // kv mapping: m=f (wm2=(w&1)*64 -> chunk w&1), n=d
    int wn2 = (w >> 1) * 16;
    int brow2 = wn2 + rr + (sub >> 1) * 8;
    uint32_t kpch = (uint32_t)(w & 1) * 16384;
    int r0row = lane >> 2, c0 = (lane & 3) * 2;

    float acc2[4][2][4];
#pragma unroll
    for (int i = 0; i < 4; i++)
#pragma unroll
        for (int j = 0; j < 2; j++)
#pragma unroll
            for (int c = 0; c < 4; c++) acc2[i][j][c] = 0.f;

    const int wneed[4] = {1, 2, 2, 0};
    for (int it = 0; it < 4; it++){
        int a = wneed[it];
        if (a >= 2) cpa_wait2(); else if (a == 1) cpa_wait1(); else cpa_wait0();
        __syncthreads();                                   // sync#1

        uint32_t kst = sb + FKV_KST + (uint32_t)(it & 1) * 32768;
        uint32_t vst = sb + FKV_VST + (uint32_t)(it & 1) * 32768;

        // ---- feat MMA: acc[t][f], K=64 ----
        float acc[4][4][4];
#pragma unroll
        for (int i = 0; i < 4; i++)
#pragma unroll
            for (int j = 0; j < 4; j++)
#pragma unroll
                for (int c = 0; c < 4; c++) acc[i][j][c] = 0.f;
#pragma unroll
        for (int ks = 0; ks < 4; ks++){
            uint32_t ahf[4][4], alf[4][4], bhf[4][2], blf[4][2];
#pragma unroll
            for (int i = 0; i < 4; i++){
                uint32_t sa = swz((uint32_t)((arow + i*16)*128 + acb0 + ks*32));
                ldsm4(ahf[i][0], ahf[i][1], ahf[i][2], ahf[i][3], kst + sa);
                ldsm4(alf[i][0], alf[i][1], alf[i][2], alf[i][3], kst + 16384 + sa);
            }
#pragma unroll
            for (int j2 = 0; j2 < 2; j2++){
                uint32_t sa = swz((uint32_t)((brow + j2*16)*128 + bcb0 + ks*32));
                uint32_t r0, r1, r2, r3;
                ldsm4(r0, r1, r2, r3, sb + FKV_PJH + sa);
                bhf[j2*2][0] = r0; bhf[j2*2][1] = r1; bhf[j2*2+1][0] = r2; bhf[j2*2+1][1] = r3;
                ldsm4(r0, r1, r2, r3, sb + FKV_PJL + sa);
                blf[j2*2][0] = r0; blf[j2*2][1] = r1; blf[j2*2+1][0] = r2; blf[j2*2+1][1] = r3;
            }
#pragma unroll
            for (int i = 0; i < 4; i++)
#pragma unroll
                for (int j = 0; j < 4; j++){
                    mma_bf16(acc[i][j], ahf[i], bhf[j]);
                    mma_bf16(acc[i][j], ahf[i], blf[j]);
                    mma_bf16(acc[i][j], alf[i], bhf[j]);
                }
        }

        // ---- exp + Ksum partials + conflict-free [t][f] split store ----
        float kp[8];
#pragma unroll
        for (int e = 0; e < 8; e++) kp[e] = 0.f;
#pragma unroll
        for (int i = 0; i < 4; i++)
#pragma unroll
            for (int j = 0; j < 4; j++)
#pragma unroll
                for (int half = 0; half < 2; half++){
                    int trow = wm + i*16 + r0row + half*8;
                    int f0 = wn + j*8 + c0;
                    float v0 = __expf(acc[i][j][half*2]) + EPS;
                    float v1 = __expf(acc[i][j][half*2 + 1]) + EPS;
                    kp[j*2]     += v0;
                    kp[j*2 + 1] += v1;
                    bf h0, l0, h1, l1;
                    split2(v0, h0, l0); split2(v1, h1, l1);
                    uint32_t addr = (uint32_t)((f0 >> 6)*16384) + swz((uint32_t)(trow*128 + (f0 & 63)*2));
                    *(__nv_bfloat162*)(dsm + FKV_KPH + addr) = __nv_bfloat162{h0, h1};
                    *(__nv_bfloat162*)(dsm + FKV_KPL + addr) = __nv_bfloat162{l0, l1};
                }
        // reduce over t (across r0row groups), then smem atomics (lanes 0-3)
#pragma unroll
        for (int e = 0; e < 8; e++){
            float v = kp[e];
            v += __shfl_xor_sync(0xffffffffu, v, 4);
            v += __shfl_xor_sync(0xffffffffu, v, 8);
            v += __shfl_xor_sync(0xffffffffu, v, 16);
            if (lane < 4)
                atomicAdd(&sksum[wn + (e >> 1)*8 + lane*2 + (e & 1)], v);
        }
        __syncthreads();                                   // sync#2: Kp visible, K stage consumed
        if (it + 2 < 4){ loadK(it & 1, it + 2); cpa_commit(); }

        // ---- KV MMA: acc2[f][d] += Kp^T @ V^T, K=128 (t), A via ldmatrix.trans ----
#pragma unroll
        for (int ks = 0; ks < 8; ks++){
            int tl = (ks & 3) * 16;
            uint32_t vch = (uint32_t)(ks >> 2) * 8192;
            uint32_t ahf[4][4], alf[4][4], bhf[2][2], blf[2][2];
#pragma unroll
            for (int i = 0; i < 4; i++){
                int fcol = i*16 + (sub & 1)*8;
                int trow = ks*16 + (sub >> 1)*8 + rr;
                uint32_t sa = kpch + swz((uint32_t)(trow*128 + fcol*2));
                ldsm4t(ahf[i][0], ahf[i][1], ahf[i][2], ahf[i][3], sb + FKV_KPH + sa);
                ldsm4t(alf[i][0], alf[i][1], alf[i][2], alf[i][3], sb + FKV_KPL + sa);
            }
            {
                uint32_t sa = vch + swz((uint32_t)(brow2*128 + tl*2 + (sub & 1)*16));
                uint32_t r0, r1, r2, r3;
                ldsm4(r0, r1, r2, r3, vst + sa);
                bhf[0][0] = r0; bhf[0][1] = r1; bhf[1][0] = r2; bhf[1][1] = r3;
                ldsm4(r0, r1, r2, r3, vst + 16384 + sa);
                blf[0][0] = r0; blf[0][1] = r1; blf[1][0] = r2; blf[1][1] = r3;
            }
#pragma unroll
            for (int i = 0; i < 4; i++)
#pragma unroll
                for (int j = 0; j < 2; j++){
                    mma_bf16(acc2[i][j], ahf[i], bhf[j]);
                    mma_bf16(acc2[i][j], ahf[i], blf[j]);
                    mma_bf16(acc2[i][j], alf[i], bhf[j]);
                }
        }
        __syncthreads();                                   // sync#3: V stage consumed
        if (it + 2 < 4){ loadV(it & 1, it + 2); cpa_commit(); }
    }

    // ---- epilogue: acc2 [f][d] -> fb -> atomicAdd g_KVt[bh][d][f]; Ksum flush ----
    float* fb = (float*)(dsm + FKV_KST);   // 128 x 65 fp32
#pragma unroll
    for (int i = 0; i < 4; i++)
#pragma unroll
        for (int j = 0; j < 2; j++)
#pragma unroll
            for (int half = 0; half < 2; half++){
                int f = (w & 1)*64 + i*16 + r0row + half*8;
                int d = wn2 + j*8 + c0;
                fb[f*65 + d]     = acc2[i][j][half*2];
                fb[f*65 + d + 1] = acc2[i][j][half*2 + 1];
            }
    __syncthreads();
    for (int idx = tid; idx < 8192; idx += 256){
        int d = idx >> 7, f = idx & 127;
        atomicAdd(&g_KVt[((size_t)bh*64 + d)*Ff + n0 + f], fb[f*65 + d]);
    }
    if (tid < 128) atomicAdd(&g_Ksum[bh*Ff + n0 + tid], sksum[tid]);
}

// ================= k_fattn: fused Qp + attn (R16 winner) =================
#define FA_KVH   0
#define FA_KVL   32768
#define FA_QH    65536
#define FA_QL    81920
#define FA_PJH   98304
#define FA_PJL   131072
#define FA_QPH   163840
#define FA_QPL   196608
#define FA_DEN   229376
#define FA_KS    229888
#define FATTN_DSM 230912

__global__ __launch_bounds__(256, 1) void k_fattn(){
    extern __shared__ __align__(1024) char dsm[];
    uint32_t sb = s2u(dsm);
    float* sden = (float*)(dsm + FA_DEN);
    float* sKs  = (float*)(dsm + FA_KS);
    int tid = threadIdx.x, lane = tid & 31, w = tid >> 5;
    int bh = blockIdx.z;
    int t0 = blockIdx.x * 128;
    int b = bh >> 4, h = bh & 15;
    int qrow0 = b*Tt + t0;
    int kvrow0 = bh*64;

    if (tid < 128) sden[tid] = 0.f;
    sKs[tid] = g_Ksum[bh*Ff + tid];

#pragma unroll
    for (int i = 0; i < 8; i++){
        int idx = tid + i*256;
        int ch = idx >> 9, r = (idx >> 3) & 63, kc = idx & 7;
        uint32_t sa = (uint32_t)(ch*8192) + swz((uint32_t)(r*128 + kc*16));
        cpa16(sb + FA_KVH + sa, g_KVth + (size_t)(kvrow0 + r)*Ff + ch*64 + kc*8);
        cpa16(sb + FA_KVL + sa, g_KVtl + (size_t)(kvrow0 + r)*Ff + ch*64 + kc*8);
    }
    load_tileN<128>(sb + FA_QH, g_Qh + h*Dd, qrow0, Ee, 0, tid);
    load_tileN<128>(sb + FA_QL, g_Ql + h*Dd, qrow0, Ee, 0, tid);
    load_tileN<256>(sb + FA_PJH, g_ph, 0, Dd, 0, tid);
    load_tileN<256>(sb + FA_PJL, g_pl, 0, Dd, 0, tid);
    cpa_commit();
    cpa_wait0();
    __syncthreads();

    int rr = lane & 7, sub = lane >> 3;
    int wm = (w & 1) * 64;
    int wn = (w >> 1) * 32;
    int wn2 = (w >> 1) * 16;
    int arow = wm + rr + (sub & 1) * 8;
    int acb0 = (sub >> 1) * 16;
    int brow = wn + rr + (sub >> 1) * 8;
    int bcb0 = (sub & 1) * 16;
    int brow2 = wn2 + rr + (sub >> 1) * 8;
    int r0row = lane >> 2, c0 = (lane & 3) * 2;

    float acc2[4][2][4];
#pragma unroll
    for (int i = 0; i < 4; i++)
#pragma unroll
        for (int j = 0; j < 2; j++)
#pragma unroll
            for (int c = 0; c < 4; c++) acc2[i][j][c] = 0.f;

    for (int fh = 0; fh < 2; fh++){
        float acc[4][4][4];
#pragma unroll
        for (int i = 0; i < 4; i++)
#pragma unroll
            for (int j = 0; j < 4; j++)
#pragma unroll
                for (int c = 0; c < 4; c++) acc[i][j][c] = 0.f;
#pragma unroll
        for (int ks = 0; ks < 4; ks++){
            uint32_t ahf[4][4], alf[4][4], bhf[4][2], blf[4][2];
#pragma unroll
            for (int i = 0; i < 4; i++){
                uint32_t sa = swz((uint32_t)((arow + i*16)*128 + acb0 + ks*32));
                ldsm4(ahf[i][0], ahf[i][1], ahf[i][2], ahf[i][3], sb + FA_QH + sa);
                ldsm4(alf[i][0], alf[i][1], alf[i][2], alf[i][3], sb + FA_QL + sa);
            }
#pragma unroll
            for (int j2 = 0; j2 < 2; j2++){
                uint32_t sa = (uint32_t)(fh*16384) + swz((uint32_t)((brow + j2*16)*128 + bcb0 + ks*32));
                uint32_t r0, r1, r2, r3;
                ldsm4(r0, r1, r2, r3, sb + FA_PJH + sa);
                bhf[j2*2][0] = r0; bhf[j2*2][1] = r1; bhf[j2*2+1][0] = r2; bhf[j2*2+1][1] = r3;
                ldsm4(r0, r1, r2, r3, sb + FA_PJL + sa);
                blf[j2*2][0] = r0; blf[j2*2][1] = r1; blf[j2*2+1][0] = r2; blf[j2*2+1][1] = r3;
            }
#pragma unroll
            for (int i = 0; i < 4; i++)
#pragma unroll
                for (int j = 0; j < 4; j++){
                    mma_bf16(acc[i][j], ahf[i], bhf[j]);
                    mma_bf16(acc[i][j], ahf[i], blf[j]);
                    mma_bf16(acc[i][j], alf[i], bhf[j]);
                }
        }

        float dloc[8];
#pragma unroll
        for (int e = 0; e < 8; e++) dloc[e] = 0.f;
#pragma unroll
        for (int i = 0; i < 4; i++)
#pragma unroll
            for (int j = 0; j < 4; j++)
#pragma unroll
                for (int half = 0; half < 2; half++){
                    int trow = wm + i*16 + r0row + half*8;
                    int f0 = wn + j*8 + c0;
                    float v0 = __expf(acc[i][j][half*2]) + EPS;
                    float v1 = __expf(acc[i][j][half*2 + 1]) + EPS;
                    dloc[i*2 + half] += v0 * sKs[fh*128 + f0] + v1 * sKs[fh*128 + f0 + 1];
                    bf h0, l0, h1, l1;
                    split2(v0, h0, l0); split2(v1, h1, l1);
                    uint32_t addr = (uint32_t)((f0 >> 6)*16384) + swz((uint32_t)(trow*128 + (f0 & 63)*2));
                    *(__nv_bfloat162*)(dsm + FA_QPH + addr) = __nv_bfloat162{h0, h1};
                    *(__nv_bfloat162*)(dsm + FA_QPL + addr) = __nv_bfloat162{l0, l1};
                }
#pragma unroll
        for (int e = 0; e < 8; e++){
            float v = dloc[e];
            v += __shfl_xor_sync(0xffffffffu, v, 1);
            v += __shfl_xor_sync(0xffffffffu, v, 2);
            if ((lane & 3) == 0)
                atomicAdd(&sden[wm + (e >> 1)*16 + r0row + (e & 1)*8], v);
        }
        __syncthreads();

#pragma unroll
        for (int kc = 0; kc < 2; kc++){
            uint32_t qa = FA_QPH + (uint32_t)kc*16384;
            uint32_t ql = FA_QPL + (uint32_t)kc*16384;
            uint32_t va = FA_KVH + (uint32_t)(fh*2 + kc)*8192;
            uint32_t vl = FA_KVL + (uint32_t)(fh*2 + kc)*8192;
#pragma unroll
            for (int ks = 0; ks < 4; ks++){
                uint32_t ahf[4][4], alf[4][4], bhf[2][2], blf[2][2];
#pragma unroll
                for (int i = 0; i < 4; i++){
                    uint32_t sa = swz((uint32_t)((arow + i*16)*128 + acb0 + ks*32));
                    ldsm4(ahf[i][0], ahf[i][1], ahf[i][2], ahf[i][3], sb + qa + sa);
                    ldsm4(alf[i][0], alf[i][1], alf[i][2], alf[i][3], sb + ql + sa);
                }
                {
                    uint32_t sa = swz((uint32_t)(brow2*128 + bcb0 + ks*32));
                    uint32_t r0, r1, r2, r3;
                    ldsm4(r0, r1, r2, r3, sb + va + sa);
                    bhf[0][0] = r0; bhf[0][1] = r1; bhf[1][0] = r2; bhf[1][1] = r3;
                    ldsm4(r0, r1, r2, r3, sb + vl + sa);
                    blf[0][0] = r0; blf[0][1] = r1; blf[1][0] = r2; blf[1][1] = r3;
                }
#pragma unroll
                for (int i = 0; i < 4; i++)
#pragma unroll
                    for (int j = 0; j < 2; j++){
                        mma_bf16(acc2[i][j], ahf[i], bhf[j]);
                        mma_bf16(acc2[i][j], ahf[i], blf[j]);
                        mma_bf16(acc2[i][j], alf[i], bhf[j]);
                    }
            }
        }
        if (fh == 0) __syncthreads();
    }

    __syncthreads();
#pragma unroll
    for (int i = 0; i < 4; i++)
#pragma unroll
        for (int half = 0; half < 2; half++){
            int row = wm + i*16 + r0row + half*8;
            float inv = 1.0f / fmaxf(sden[row], 1e-6f);
#pragma unroll
            for (int j = 0; j < 2; j++){
                int col = wn2 + j*8 + c0;
                bf h0, l0, h1, l1;
                split2(acc2[i][j][half*2] * inv, h0, l0);
                split2(acc2[i][j][half*2 + 1] * inv, h1, l1);
                size_t o = (size_t)(b*Tt + t0 + row)*Ee + h*Dd + col;
                *(__nv_bfloat162*)&g_ah[o] = __nv_bfloat162{h0, h1};
                *(__nv_bfloat162*)&g_al[o] = __nv_bfloat162{l0, l1};
            }
        }
}

// ================= launch =================
extern "C" void kernel_launch(void* const* d_in, const int* in_sizes, int n_in,
                              void* d_out, int out_size) {
    const float* x    = (const float*)d_in[0];
    const float* Wq   = (const float*)d_in[1];
    const float* Wk   = (const float*)d_in[2];
    const float* Wv   = (const float*)d_in[3];
    const float* Wo   = (const float*)d_in[4];
    const float* proj = (const float*)d_in[5];
    float* out = (float*)d_out;

    cudaFuncSetAttribute(k_mmaP<0>, cudaFuncAttributeMaxDynamicSharedMemorySize, PERS_DSM);
    cudaFuncSetAttribute(k_mmaP<1>, cudaFuncAttributeMaxDynamicSharedMemorySize, PERS_DSM);
    cudaFuncSetAttribute(k_featKV,  cudaFuncAttributeMaxDynamicSharedMemorySize, FKV_DSM);
    cudaFuncSetAttribute(k_fattn,   cudaFuncAttributeMaxDynamicSharedMemorySize, FATTN_DSM);

    k_prep_proj<<<(Bb*Hh*64*Ff + 255)/256, 256>>>(proj);
    k_prep_x<<<dim3(Tt/32, Cc/32, Bb), dim3(32, 8)>>>(x, out);
    k_prep_w<<<dim3(Ee/32, Ee/32, 4), dim3(32, 8)>>>(Wq, Wk, Wv, Wo);

    k_mmaP<0><<<148, 256, PERS_DSM>>>(nullptr);                            // QKV (persistent)
    k_featKV<<<dim3(Tt/512, Ff/128, Bb*Hh), 256, FKV_DSM>>>();             // Kp -> KV + Ksum (fused, no Kp gmem)
    k_cvt_kv<<<(Bb*Hh*64*Ff + 255)/256, 256>>>();
    k_fattn<<<dim3(Tt/128, 1, Bb*Hh), 256, FATTN_DSM>>>();                 // Qp + attn (fused)
    k_mmaP<1><<<148, 256, PERS_DSM>>>(out);                                // Wo + concat (persistent)
}